// round 2
// baseline (speedup 1.0000x reference)
#include <cuda_runtime.h>
#include <math.h>

#define NN 20000
#define ED 160000
#define MAXE 160000
#define BN_BLOCKS 2500   /* ceil(MAXE/64) */

/* ------------------------------ static scratch ------------------------------ */
__device__ int g_cnt[NN];
__device__ int g_fill1[NN], g_fill2[NN], g_fill3[NN], g_fill4[NN];
__device__ int g_offA[NN], g_offB[NN];
__device__ int g_bucket[ED];
__device__ int g_csrc[MAXE], g_cdst[MAXE];
__device__ int g_ndeg[NN], g_incoff[NN];
__device__ int g_inc[2 * MAXE];
__device__ float g_dinv[MAXE];
__device__ float g_xW[NN * 64];
__device__ float g_hE[MAXE * 64];
__device__ float g_aggN[NN * 64];
__device__ double g_p1[BN_BLOCKS * 64], g_p2[BN_BLOCKS * 64];
__device__ float g_mu[64], g_istd[64];
__device__ float g_h2[MAXE], g_agg2[NN], g_score[MAXE];
__device__ unsigned g_keyv[MAXE];
__device__ int g_hist[256];
__device__ unsigned long long g_packed[NN];
__device__ int g_sel[MAXE];
__device__ int g_n2c[NN], g_flag[NN], g_rankv[NN], g_uniq[NN], g_ni[NN];
__device__ int g_pcnt[NN], g_poff[NN], g_pnode[NN];
__device__ int g_ecnt[NN], g_eoffA[NN], g_eoffB[NN];
__device__ int g_E, g_M, g_P;
__device__ int g_k, g_krem, g_c1;
__device__ unsigned g_prefix;

/* ------------------------------ init ------------------------------ */
__global__ void k_init() {
    int i = blockIdx.x * blockDim.x + threadIdx.x;
    if (i < NN) {
        g_cnt[i] = 0; g_fill1[i] = 0; g_fill2[i] = 0; g_fill3[i] = 0; g_fill4[i] = 0;
        g_ndeg[i] = 0; g_ecnt[i] = 0; g_pcnt[i] = 0; g_flag[i] = 0;
        g_packed[i] = ~0ull;
    }
    if (i < 256) g_hist[i] = 0;
}

/* ------------------------------ generic single-block exclusive scan ------------------------------ */
__global__ void k_scan(const int* __restrict__ in, int* __restrict__ out, int n, int sel_total) {
    __shared__ int ws[32];
    __shared__ int carry;
    int t = threadIdx.x, lane = t & 31, w = t >> 5;
    if (t == 0) carry = 0;
    __syncthreads();
    for (int base = 0; base < n; base += 1024) {
        int i = base + t;
        int v = (i < n) ? in[i] : 0;
        int x = v;
        #pragma unroll
        for (int o = 1; o < 32; o <<= 1) { int y = __shfl_up_sync(0xffffffffu, x, o); if (lane >= o) x += y; }
        if (lane == 31) ws[w] = x;
        __syncthreads();
        if (w == 0) {
            int s = ws[lane];
            #pragma unroll
            for (int o = 1; o < 32; o <<= 1) { int y = __shfl_up_sync(0xffffffffu, s, o); if (lane >= o) s += y; }
            ws[lane] = s;
        }
        __syncthreads();
        int woff = (w == 0) ? 0 : ws[w - 1];
        if (i < n) out[i] = carry + woff + x - v;
        __syncthreads();
        if (t == 0) carry += ws[31];
        __syncthreads();
    }
    if (t == 0) {
        if (sel_total == 1) g_E = carry;
        else if (sel_total == 2) g_M = carry;
        else if (sel_total == 3) g_P = carry;
    }
}

/* ------------------------------ generic per-bucket insertion sort (+optional dedup) ------------------------------ */
__global__ void k_sort(int* data, const int* __restrict__ off, int* len, int n, int dedup) {
    int u = blockIdx.x * blockDim.x + threadIdx.x;
    if (u >= n) return;
    int o = off[u], L = len[u];
    for (int i = 1; i < L; i++) {
        int key = data[o + i]; int j = i - 1;
        while (j >= 0 && data[o + j] > key) { data[o + j + 1] = data[o + j]; j--; }
        data[o + j + 1] = key;
    }
    if (dedup) {
        int m = 0;
        for (int i = 0; i < L; i++) {
            int v = data[o + i];
            if (m == 0 || v != data[o + m - 1]) data[o + m++] = v;
        }
        len[u] = m;
    }
}

/* ------------------------------ stage 1: clean (dedup) undirected edges ------------------------------ */
__global__ void k_hist_u(const int* __restrict__ ei) {
    int i = blockIdx.x * blockDim.x + threadIdx.x;
    if (i >= ED) return;
    int s = ei[i], d = ei[ED + i];
    if (s < d) atomicAdd(&g_cnt[s], 1);
}
__global__ void k_scatter_u(const int* __restrict__ ei) {
    int i = blockIdx.x * blockDim.x + threadIdx.x;
    if (i >= ED) return;
    int s = ei[i], d = ei[ED + i];
    if (s < d) {
        int pos = g_offA[s] + atomicAdd(&g_fill1[s], 1);
        g_bucket[pos] = d;
    }
}
__global__ void k_compact() {
    int u = blockIdx.x * blockDim.x + threadIdx.x;
    if (u >= NN) return;
    int L = g_cnt[u], ob = g_offB[u], oa = g_offA[u];
    for (int j = 0; j < L; j++) { g_csrc[ob + j] = u; g_cdst[ob + j] = g_bucket[oa + j]; }
}
__global__ void k_ndeg() {
    int e = blockIdx.x * blockDim.x + threadIdx.x;
    if (e >= MAXE || e >= g_E) return;
    atomicAdd(&g_ndeg[g_csrc[e]], 1);
    atomicAdd(&g_ndeg[g_cdst[e]], 1);
}
__global__ void k_incscat() {
    int e = blockIdx.x * blockDim.x + threadIdx.x;
    if (e >= MAXE || e >= g_E) return;
    int u = g_csrc[e], v = g_cdst[e];
    int p1 = g_incoff[u] + atomicAdd(&g_fill2[u], 1); g_inc[p1] = e;
    int p2 = g_incoff[v] + atomicAdd(&g_fill2[v], 1); g_inc[p2] = e;
}
__global__ void k_dinv() {
    int e = blockIdx.x * blockDim.x + threadIdx.x;
    if (e >= MAXE || e >= g_E) return;
    int deg = g_ndeg[g_csrc[e]] + g_ndeg[g_cdst[e]] - 1;
    if (deg < 1) deg = 1;
    g_dinv[e] = 1.0f / sqrtf((float)deg);
}

/* ------------------------------ stage 2: features ------------------------------ */
__global__ void k_gemm(const float* __restrict__ x, const float* __restrict__ W) {
    __shared__ float sW[128 * 64];
    __shared__ float sx[4][128];
    int t = threadIdx.x;
    for (int i = t; i < 128 * 64; i += 256) sW[i] = W[i];
    int r0 = blockIdx.x * 4;
    for (int i = t; i < 4 * 128; i += 256) {
        int rr = i >> 7, kk = i & 127; int r = r0 + rr;
        sx[rr][kk] = (r < NN) ? x[r * 128 + kk] : 0.f;
    }
    __syncthreads();
    int c = t & 63, rr = t >> 6;
    int r = r0 + rr;
    if (r < NN) {
        float acc = 0.f;
        #pragma unroll
        for (int k2 = 0; k2 < 128; k2++) acc += sx[rr][k2] * sW[k2 * 64 + c];
        g_xW[r * 64 + c] = acc;
    }
}
__global__ void k_edge_h() {
    int idx = blockIdx.x * blockDim.x + threadIdx.x;
    if (idx >= MAXE * 64) return;
    int e = idx >> 6; if (e >= g_E) return;
    int c = idx & 63;
    g_hE[idx] = 0.5f * (g_xW[g_csrc[e] * 64 + c] + g_xW[g_cdst[e] * 64 + c]);
}
__global__ void k_aggN() {
    int idx = blockIdx.x * blockDim.x + threadIdx.x;
    if (idx >= NN * 64) return;
    int n = idx >> 6, c = idx & 63;
    int o = g_incoff[n], L = g_ndeg[n];
    float s = 0.f;
    for (int j = 0; j < L; j++) { int e = g_inc[o + j]; s += g_dinv[e] * g_hE[e * 64 + c]; }
    g_aggN[idx] = s;
}
__global__ void k_conv1(const float* __restrict__ b1) {
    int idx = blockIdx.x * blockDim.x + threadIdx.x;
    if (idx >= MAXE * 64) return;
    int e = idx >> 6; if (e >= g_E) return;
    int c = idx & 63;
    float di = g_dinv[e];
    float h = g_hE[idx];
    g_hE[idx] = di * (g_aggN[g_csrc[e] * 64 + c] + g_aggN[g_cdst[e] * 64 + c]) - di * di * h + b1[c];
}
__global__ void k_bn_part() {
    int blk = blockIdx.x, t = threadIdx.x;
    int c = t & 63, el = t >> 6;
    int E = g_E;
    double s = 0.0, s2 = 0.0;
    int e0 = blk * 64;
    for (int j = 0; j < 16; j++) {
        int e = e0 + el + j * 4;
        if (e < E) { double v = (double)g_hE[e * 64 + c]; s += v; s2 += v * v; }
    }
    __shared__ double sh[256], sh2[256];
    sh[t] = s; sh2[t] = s2;
    __syncthreads();
    if (t < 64) {
        g_p1[blk * 64 + t] = sh[t] + sh[t + 64] + sh[t + 128] + sh[t + 192];
        g_p2[blk * 64 + t] = sh2[t] + sh2[t + 64] + sh2[t + 128] + sh2[t + 192];
    }
}
__global__ void k_bn_final() {
    int c = threadIdx.x;
    double s = 0.0, s2 = 0.0;
    for (int b = 0; b < BN_BLOCKS; b++) { s += g_p1[b * 64 + c]; s2 += g_p2[b * 64 + c]; }
    double Ed = (double)g_E;
    double mu = s / Ed;
    double var = s2 / Ed - mu * mu;
    g_mu[c] = (float)mu;
    g_istd[c] = (float)(1.0 / sqrt(var + 1e-5));
    if (c == 0) {
        int E = g_E;
        int k = E / 2;
        if (k > NN / 2) k = NN / 2;
        if (k < 1) k = 1;
        g_k = k; g_krem = k; g_c1 = 0; g_prefix = 0u;
    }
}
__global__ void k_bnrelu_dot(const float* __restrict__ gamma, const float* __restrict__ beta,
                             const float* __restrict__ W2) {
    int gt = blockIdx.x * blockDim.x + threadIdx.x;
    int e = gt >> 5, lane = gt & 31;
    if (e >= g_E) return;
    float a = g_hE[e * 64 + lane];
    float b = g_hE[e * 64 + 32 + lane];
    a = gamma[lane] * (a - g_mu[lane]) * g_istd[lane] + beta[lane]; a = fmaxf(a, 0.f);
    b = gamma[lane + 32] * (b - g_mu[lane + 32]) * g_istd[lane + 32] + beta[lane + 32]; b = fmaxf(b, 0.f);
    float d = a * W2[lane] + b * W2[lane + 32];
    #pragma unroll
    for (int o = 16; o > 0; o >>= 1) d += __shfl_down_sync(0xffffffffu, d, o);
    if (lane == 0) g_h2[e] = d;
}
__global__ void k_agg2() {
    int n = blockIdx.x * blockDim.x + threadIdx.x;
    if (n >= NN) return;
    int o = g_incoff[n], L = g_ndeg[n];
    float s = 0.f;
    for (int j = 0; j < L; j++) { int e = g_inc[o + j]; s += g_dinv[e] * g_h2[e]; }
    g_agg2[n] = s;
}
__global__ void k_score(const float* __restrict__ b2) {
    int e = blockIdx.x * blockDim.x + threadIdx.x;
    if (e >= MAXE || e >= g_E) return;
    float di = g_dinv[e];
    float z = di * (g_agg2[g_csrc[e]] + g_agg2[g_cdst[e]]) - di * di * g_h2[e] + b2[0];
    float s = 1.0f / (1.0f + expf(-z));
    g_score[e] = s;
    g_keyv[e] = __float_as_uint(s);   /* s>0 => bit pattern is order-preserving */
}

/* ------------------------------ stage 3: top-k radix select ------------------------------ */
__global__ void k_hist_sel(int shift, unsigned maskHi) {
    int e = blockIdx.x * blockDim.x + threadIdx.x;
    if (e >= MAXE || e >= g_E) return;
    unsigned kk = g_keyv[e];
    if ((kk & maskHi) == (g_prefix & maskHi))
        atomicAdd(&g_hist[(kk >> shift) & 255], 1);
}
__global__ void k_pick(int shift) {
    if (threadIdx.x != 0 || blockIdx.x != 0) return;
    int krem = g_krem;
    int cum = 0, chosen = 0;
    for (int b = 255; b >= 0; b--) {
        int h = g_hist[b];
        if (cum + h >= krem) { chosen = b; break; }
        cum += h;
    }
    g_prefix |= ((unsigned)chosen) << shift;
    g_krem = krem - cum;
    g_c1 += cum;
    for (int b = 0; b < 256; b++) g_hist[b] = 0;
}
__global__ void k_select() {
    __shared__ int ws[32];
    __shared__ int carry;
    int t = threadIdx.x, lane = t & 31, w = t >> 5;
    unsigned T = g_prefix;
    int need = g_krem;
    int E = g_E;
    if (t == 0) carry = 0;
    __syncthreads();
    for (int base = 0; base < E; base += 1024) {
        int i = base + t;
        unsigned kk = (i < E) ? g_keyv[i] : 0u;
        int eq = (i < E && kk == T) ? 1 : 0;
        int x = eq;
        #pragma unroll
        for (int o = 1; o < 32; o <<= 1) { int y = __shfl_up_sync(0xffffffffu, x, o); if (lane >= o) x += y; }
        if (lane == 31) ws[w] = x;
        __syncthreads();
        if (w == 0) {
            int s = ws[lane];
            #pragma unroll
            for (int o = 1; o < 32; o <<= 1) { int y = __shfl_up_sync(0xffffffffu, s, o); if (lane >= o) s += y; }
            ws[lane] = s;
        }
        __syncthreads();
        int woff = (w == 0) ? 0 : ws[w - 1];
        int excl = carry + woff + x - eq;
        if (i < E) g_sel[i] = (kk > T) || (eq && excl < need);
        __syncthreads();
        if (t == 0) carry += ws[31];
        __syncthreads();
    }
}

/* ------------------------------ stage 4: clustering ------------------------------ */
__global__ void k_clmin() {
    int e = blockIdx.x * blockDim.x + threadIdx.x;
    if (e >= MAXE || e >= g_E) return;
    if (!g_sel[e]) return;
    unsigned long long pk = (((unsigned long long)g_keyv[e]) << 32) | (unsigned)(0xFFFFFFFFu - (unsigned)e);
    atomicMin(&g_packed[g_cdst[e]], pk);
}
__global__ void k_n2c() {
    int n = blockIdx.x * blockDim.x + threadIdx.x;
    if (n >= NN) return;
    unsigned long long pk = g_packed[n];
    int v;
    if (pk != ~0ull) {
        unsigned e = 0xFFFFFFFFu - (unsigned)(pk & 0xFFFFFFFFull);
        v = g_csrc[e];
    } else v = n;
    g_n2c[n] = v;
    g_flag[v] = 1;
}
__global__ void k_maps() {
    int n = blockIdx.x * blockDim.x + threadIdx.x;
    if (n >= NN) return;
    if (g_flag[n]) g_uniq[g_rankv[n]] = n;
    g_ni[n] = g_rankv[g_n2c[n]];
}

/* ------------------------------ stage 5: node pooling ------------------------------ */
__global__ void k_pcnt() {
    int n = blockIdx.x * blockDim.x + threadIdx.x;
    if (n >= NN) return;
    atomicAdd(&g_pcnt[g_ni[n]], 1);
}
__global__ void k_pscat() {
    int n = blockIdx.x * blockDim.x + threadIdx.x;
    if (n >= NN) return;
    int m = g_ni[n];
    int pos = g_poff[m] + atomicAdd(&g_fill3[m], 1);
    g_pnode[pos] = n;
}
__global__ void k_xpool(const float* __restrict__ x, float* __restrict__ out) {
    int idx = blockIdx.x * blockDim.x + threadIdx.x;
    if (idx >= NN * 128) return;
    int m = idx >> 7, c = idx & 127;
    if (m >= g_M) return;
    int o = g_poff[m], L = g_pcnt[m];
    float s = 0.f;
    for (int j = 0; j < L; j++) s += x[g_pnode[o + j] * 128 + c];
    out[m * 128 + c] = s / (float)L;
}

/* ------------------------------ stage 6: pooled edges ------------------------------ */
__global__ void k_ehist(const int* __restrict__ ei) {
    int i = blockIdx.x * blockDim.x + threadIdx.x;
    if (i >= ED) return;
    int ns = g_ni[ei[i]], nd = g_ni[ei[ED + i]];
    if (ns != nd) atomicAdd(&g_ecnt[ns], 1);
}
__global__ void k_escat(const int* __restrict__ ei) {
    int i = blockIdx.x * blockDim.x + threadIdx.x;
    if (i >= ED) return;
    int ns = g_ni[ei[i]], nd = g_ni[ei[ED + i]];
    if (ns != nd) {
        int pos = g_eoffA[ns] + atomicAdd(&g_fill4[ns], 1);
        g_bucket[pos] = nd;
    }
}
__global__ void k_ewrite(float* __restrict__ out) {
    int m = blockIdx.x * blockDim.x + threadIdx.x;
    if (m >= NN || m >= g_M) return;
    int L = g_ecnt[m], ob = g_eoffB[m], oa = g_eoffA[m];
    long base = 128L * g_M;
    int P = g_P;
    for (int j = 0; j < L; j++) {
        out[base + ob + j] = (float)m;
        out[base + P + ob + j] = (float)g_bucket[oa + j];
    }
}

/* ------------------------------ stage 7: tail outputs ------------------------------ */
__global__ void k_tail(const int* __restrict__ batch, float* __restrict__ out) {
    int i = blockIdx.x * blockDim.x + threadIdx.x;
    if (i >= MAXE) return;
    int E = g_E, M = g_M, P = g_P;
    long base = 128L * M + 2L * P;
    if (i < M) out[base + i] = (float)batch[g_uniq[i]];
    if (i < E) out[base + M + i] = g_score[i];
    if (i < NN) out[base + M + E + i] = (float)g_ni[i];
}

/* ------------------------------ launch ------------------------------ */
extern "C" void kernel_launch(void* const* d_in, const int* in_sizes, int n_in,
                              void* d_out, int out_size) {
    const float* x      = (const float*)d_in[0];
    const float* W1     = (const float*)d_in[1];
    const float* b1     = (const float*)d_in[2];
    const float* gamma1 = (const float*)d_in[3];
    const float* beta1  = (const float*)d_in[4];
    const float* W2     = (const float*)d_in[5];
    const float* b2     = (const float*)d_in[6];
    const int*   ei     = (const int*)d_in[7];
    const int*   batch  = (const int*)d_in[8];
    float* out = (float*)d_out;

    void* p;
    int *cnt, *offA, *offB, *bucket, *ndeg, *incoff, *inc, *flag, *rankv;
    int *pcnt, *poff, *pnode, *ecnt, *eoffA, *eoffB;
    cudaGetSymbolAddress(&p, g_cnt);    cnt    = (int*)p;
    cudaGetSymbolAddress(&p, g_offA);   offA   = (int*)p;
    cudaGetSymbolAddress(&p, g_offB);   offB   = (int*)p;
    cudaGetSymbolAddress(&p, g_bucket); bucket = (int*)p;
    cudaGetSymbolAddress(&p, g_ndeg);   ndeg   = (int*)p;
    cudaGetSymbolAddress(&p, g_incoff); incoff = (int*)p;
    cudaGetSymbolAddress(&p, g_inc);    inc    = (int*)p;
    cudaGetSymbolAddress(&p, g_flag);   flag   = (int*)p;
    cudaGetSymbolAddress(&p, g_rankv);  rankv  = (int*)p;
    cudaGetSymbolAddress(&p, g_pcnt);   pcnt   = (int*)p;
    cudaGetSymbolAddress(&p, g_poff);   poff   = (int*)p;
    cudaGetSymbolAddress(&p, g_pnode);  pnode  = (int*)p;
    cudaGetSymbolAddress(&p, g_ecnt);   ecnt   = (int*)p;
    cudaGetSymbolAddress(&p, g_eoffA);  eoffA  = (int*)p;
    cudaGetSymbolAddress(&p, g_eoffB);  eoffB  = (int*)p;

    const int B = 256;
    const int gN  = (NN + B - 1) / B;
    const int gED = (ED + B - 1) / B;
    const int gE  = (MAXE + B - 1) / B;
    const int gEC = (MAXE * 64 + B - 1) / B;
    const int gNC = (NN * 64 + B - 1) / B;

    k_init<<<gN, B>>>();

    /* stage 1: clean edges + incidence CSR */
    k_hist_u<<<gED, B>>>(ei);
    k_scan<<<1, 1024>>>(cnt, offA, NN, 0);
    k_scatter_u<<<gED, B>>>(ei);
    k_sort<<<gN, B>>>(bucket, offA, cnt, NN, 1);
    k_scan<<<1, 1024>>>(cnt, offB, NN, 1);          /* -> g_E */
    k_compact<<<gN, B>>>();
    k_ndeg<<<gE, B>>>();
    k_scan<<<1, 1024>>>(ndeg, incoff, NN, 0);
    k_incscat<<<gE, B>>>();
    k_sort<<<gN, B>>>(inc, incoff, ndeg, NN, 0);
    k_dinv<<<gE, B>>>();

    /* stage 2: features / GCN / BN / scores */
    k_gemm<<<NN / 4, B>>>(x, W1);
    k_edge_h<<<gEC, B>>>();
    k_aggN<<<gNC, B>>>();
    k_conv1<<<gEC, B>>>(b1);
    k_bn_part<<<BN_BLOCKS, B>>>();
    k_bn_final<<<1, 64>>>();
    k_bnrelu_dot<<<(MAXE * 32 + B - 1) / B, B>>>(gamma1, beta1, W2);
    k_agg2<<<gN, B>>>();
    k_score<<<gE, B>>>(b2);

    /* stage 3: top-k radix select (MSB-first, 4x8 bits) */
    for (int pidx = 0; pidx < 4; pidx++) {
        int shift = 24 - 8 * pidx;
        unsigned maskHi = (pidx == 0) ? 0u : (0xFFFFFFFFu << (shift + 8));
        k_hist_sel<<<gE, B>>>(shift, maskHi);
        k_pick<<<1, 1>>>(shift);
    }
    k_select<<<1, 1024>>>();

    /* stage 4: clustering */
    k_clmin<<<gE, B>>>();
    k_n2c<<<gN, B>>>();
    k_scan<<<1, 1024>>>(flag, rankv, NN, 2);        /* -> g_M */
    k_maps<<<gN, B>>>();

    /* stage 5: node pooling */
    k_pcnt<<<gN, B>>>();
    k_scan<<<1, 1024>>>(pcnt, poff, NN, 0);
    k_pscat<<<gN, B>>>();
    k_sort<<<gN, B>>>(pnode, poff, pcnt, NN, 0);
    k_xpool<<<(NN * 128 + B - 1) / B, B>>>(x, out);

    /* stage 6: pooled edges */
    k_ehist<<<gED, B>>>(ei);
    k_scan<<<1, 1024>>>(ecnt, eoffA, NN, 0);
    k_escat<<<gED, B>>>(ei);
    k_sort<<<gN, B>>>(bucket, eoffA, ecnt, NN, 1);
    k_scan<<<1, 1024>>>(ecnt, eoffB, NN, 3);        /* -> g_P */
    k_ewrite<<<gN, B>>>(out);

    /* stage 7: tail */
    k_tail<<<gE, B>>>(batch, out);

    (void)in_sizes; (void)n_in; (void)out_size;
}

// round 4
// speedup vs baseline: 1.1973x; 1.1973x over previous
#include <cuda_runtime.h>
#include <math.h>

#define NN 20000
#define ED 160000
#define MAXE 160000
#define BN_BLOCKS 2500   /* ceil(MAXE/64) */
#define MW 625           /* bitmask words for NN bits */
#define SELB 625         /* 625*256 = 160000 */

/* ------------------------------ static scratch ------------------------------ */
__device__ int g_cnt[NN];
__device__ int g_fill1[NN], g_fill2[NN], g_fill3[NN], g_fill4[NN];
__device__ int g_offA[NN], g_offB[NN];
__device__ int g_bucket[ED];
__device__ int g_csrc[MAXE], g_cdst[MAXE];
__device__ int g_ndeg[NN], g_incoff[NN];
__device__ int g_inc[2 * MAXE];
__device__ float g_dinv[MAXE];
__device__ float g_xW[NN * 64];
__device__ float g_hE[MAXE * 64];
__device__ float g_aggN[NN * 64];
__device__ double g_p1[BN_BLOCKS * 64], g_p2[BN_BLOCKS * 64];
__device__ float g_mu[64], g_istd[64];
__device__ float g_h2[MAXE], g_agg2[NN], g_score[MAXE];
__device__ unsigned g_keyv[MAXE];
__device__ int g_hist[256];
__device__ unsigned long long g_packed[NN];
__device__ int g_bcnt[SELB], g_boff[SELB];
__device__ int g_n2c[NN], g_flag[NN], g_rankv[NN], g_uniq[NN], g_ni[NN];
__device__ int g_pcnt[NN], g_poff[NN], g_pnode[NN];
__device__ int g_ecnt[NN], g_eoffA[NN], g_ucnt[NN], g_eoffB[NN];
__device__ int g_E, g_M, g_P;
__device__ int g_k, g_krem, g_c1;
__device__ unsigned g_prefix;

/* ------------------------------ init ------------------------------ */
__global__ void k_init() {
    int i = blockIdx.x * blockDim.x + threadIdx.x;
    if (i < NN) {
        g_cnt[i] = 0; g_fill1[i] = 0; g_fill2[i] = 0; g_fill3[i] = 0; g_fill4[i] = 0;
        g_ndeg[i] = 0; g_ecnt[i] = 0; g_pcnt[i] = 0; g_flag[i] = 0;
        g_packed[i] = ~0ull;
    }
    if (i < 256) g_hist[i] = 0;
}

/* ------------------------------ generic single-block exclusive scan ------------------------------ */
__global__ void k_scan(const int* __restrict__ in, int* __restrict__ out, int n, int sel_total) {
    __shared__ int ws[32];
    __shared__ int carry;
    int t = threadIdx.x, lane = t & 31, w = t >> 5;
    if (t == 0) carry = 0;
    __syncthreads();
    for (int base = 0; base < n; base += 1024) {
        int i = base + t;
        int v = (i < n) ? in[i] : 0;
        int x = v;
        #pragma unroll
        for (int o = 1; o < 32; o <<= 1) { int y = __shfl_up_sync(0xffffffffu, x, o); if (lane >= o) x += y; }
        if (lane == 31) ws[w] = x;
        __syncthreads();
        if (w == 0) {
            int s = ws[lane];
            #pragma unroll
            for (int o = 1; o < 32; o <<= 1) { int y = __shfl_up_sync(0xffffffffu, s, o); if (lane >= o) s += y; }
            ws[lane] = s;
        }
        __syncthreads();
        int woff = (w == 0) ? 0 : ws[w - 1];
        if (i < n) out[i] = carry + woff + x - v;
        __syncthreads();
        if (t == 0) carry += ws[31];
        __syncthreads();
    }
    if (t == 0) {
        if (sel_total == 1) g_E = carry;
        else if (sel_total == 2) g_M = carry;
        else if (sel_total == 3) g_P = carry;
    }
}

/* ------------------------------ per-bucket insertion sort (small buckets only) ------------------------------ */
__global__ void k_sort(int* data, const int* __restrict__ off, int* len, int n, int dedup) {
    int u = blockIdx.x * blockDim.x + threadIdx.x;
    if (u >= n) return;
    int o = off[u], L = len[u];
    for (int i = 1; i < L; i++) {
        int key = data[o + i]; int j = i - 1;
        while (j >= 0 && data[o + j] > key) { data[o + j + 1] = data[o + j]; j--; }
        data[o + j + 1] = key;
    }
    if (dedup) {
        int m = 0;
        for (int i = 0; i < L; i++) {
            int v = data[o + i];
            if (m == 0 || v != data[o + m - 1]) data[o + m++] = v;
        }
        len[u] = m;
    }
}

/* ------------------------------ stage 1: clean (dedup) undirected edges ------------------------------ */
__global__ void k_hist_u(const int* __restrict__ ei) {
    int i = blockIdx.x * blockDim.x + threadIdx.x;
    if (i >= ED) return;
    int s = ei[i], d = ei[ED + i];
    if (s < d) atomicAdd(&g_cnt[s], 1);
}
__global__ void k_scatter_u(const int* __restrict__ ei) {
    int i = blockIdx.x * blockDim.x + threadIdx.x;
    if (i >= ED) return;
    int s = ei[i], d = ei[ED + i];
    if (s < d) {
        int pos = g_offA[s] + atomicAdd(&g_fill1[s], 1);
        g_bucket[pos] = d;
    }
}
__global__ void k_compact() {   /* compact + node degrees */
    int u = blockIdx.x * blockDim.x + threadIdx.x;
    if (u >= NN) return;
    int L = g_cnt[u], ob = g_offB[u], oa = g_offA[u];
    for (int j = 0; j < L; j++) {
        int d = g_bucket[oa + j];
        g_csrc[ob + j] = u; g_cdst[ob + j] = d;
        atomicAdd(&g_ndeg[d], 1);
    }
    if (L) atomicAdd(&g_ndeg[u], L);
}
__global__ void k_incscat() {   /* incidence scatter + dinv */
    int e = blockIdx.x * blockDim.x + threadIdx.x;
    if (e >= MAXE || e >= g_E) return;
    int u = g_csrc[e], v = g_cdst[e];
    int p1 = g_incoff[u] + atomicAdd(&g_fill2[u], 1); g_inc[p1] = e;
    int p2 = g_incoff[v] + atomicAdd(&g_fill2[v], 1); g_inc[p2] = e;
    int deg = g_ndeg[u] + g_ndeg[v] - 1;
    if (deg < 1) deg = 1;
    g_dinv[e] = 1.0f / sqrtf((float)deg);
}

/* ------------------------------ stage 2: features ------------------------------ */
__global__ void k_gemm(const float* __restrict__ x, const float* __restrict__ W) {
    __shared__ float sW[128 * 64];
    __shared__ float sx[4][128];
    int t = threadIdx.x;
    for (int i = t; i < 128 * 64; i += 256) sW[i] = W[i];
    int r0 = blockIdx.x * 4;
    for (int i = t; i < 4 * 128; i += 256) {
        int rr = i >> 7, kk = i & 127; int r = r0 + rr;
        sx[rr][kk] = (r < NN) ? x[r * 128 + kk] : 0.f;
    }
    __syncthreads();
    int c = t & 63, rr = t >> 6;
    int r = r0 + rr;
    if (r < NN) {
        float acc = 0.f;
        #pragma unroll
        for (int k2 = 0; k2 < 128; k2++) acc += sx[rr][k2] * sW[k2 * 64 + c];
        g_xW[r * 64 + c] = acc;
    }
}
__global__ void k_edge_h() {
    int idx = blockIdx.x * blockDim.x + threadIdx.x;
    if (idx >= MAXE * 64) return;
    int e = idx >> 6; if (e >= g_E) return;
    int c = idx & 63;
    g_hE[idx] = 0.5f * (g_xW[g_csrc[e] * 64 + c] + g_xW[g_cdst[e] * 64 + c]);
}
__global__ void k_aggN() {
    int idx = blockIdx.x * blockDim.x + threadIdx.x;
    if (idx >= NN * 64) return;
    int n = idx >> 6, c = idx & 63;
    int o = g_incoff[n], L = g_ndeg[n];
    float s = 0.f;
    for (int j = 0; j < L; j++) { int e = g_inc[o + j]; s += g_dinv[e] * g_hE[e * 64 + c]; }
    g_aggN[idx] = s;
}
__global__ void k_conv1(const float* __restrict__ b1) {
    int idx = blockIdx.x * blockDim.x + threadIdx.x;
    if (idx >= MAXE * 64) return;
    int e = idx >> 6; if (e >= g_E) return;
    int c = idx & 63;
    float di = g_dinv[e];
    float h = g_hE[idx];
    g_hE[idx] = di * (g_aggN[g_csrc[e] * 64 + c] + g_aggN[g_cdst[e] * 64 + c]) - di * di * h + b1[c];
}
__global__ void k_bn_part() {
    int blk = blockIdx.x, t = threadIdx.x;
    int c = t & 63, el = t >> 6;
    int E = g_E;
    double s = 0.0, s2 = 0.0;
    int e0 = blk * 64;
    for (int j = 0; j < 16; j++) {
        int e = e0 + el + j * 4;
        if (e < E) { double v = (double)g_hE[e * 64 + c]; s += v; s2 += v * v; }
    }
    __shared__ double sh[256], sh2[256];
    sh[t] = s; sh2[t] = s2;
    __syncthreads();
    if (t < 64) {
        g_p1[blk * 64 + t] = sh[t] + sh[t + 64] + sh[t + 128] + sh[t + 192];
        g_p2[blk * 64 + t] = sh2[t] + sh2[t + 64] + sh2[t + 128] + sh2[t + 192];
    }
}
__global__ void k_bn_final() {
    int c = threadIdx.x;
    double s = 0.0, s2 = 0.0;
    for (int b = 0; b < BN_BLOCKS; b++) { s += g_p1[b * 64 + c]; s2 += g_p2[b * 64 + c]; }
    double Ed = (double)g_E;
    double mu = s / Ed;
    double var = s2 / Ed - mu * mu;
    g_mu[c] = (float)mu;
    g_istd[c] = (float)(1.0 / sqrt(var + 1e-5));
    if (c == 0) {
        int E = g_E;
        int k = E / 2;
        if (k > NN / 2) k = NN / 2;
        if (k < 1) k = 1;
        g_k = k; g_krem = k; g_c1 = 0; g_prefix = 0u;
    }
}
__global__ void k_bnrelu_dot(const float* __restrict__ gamma, const float* __restrict__ beta,
                             const float* __restrict__ W2) {
    int gt = blockIdx.x * blockDim.x + threadIdx.x;
    int e = gt >> 5, lane = gt & 31;
    if (e >= g_E) return;
    float a = g_hE[e * 64 + lane];
    float b = g_hE[e * 64 + 32 + lane];
    a = gamma[lane] * (a - g_mu[lane]) * g_istd[lane] + beta[lane]; a = fmaxf(a, 0.f);
    b = gamma[lane + 32] * (b - g_mu[lane + 32]) * g_istd[lane + 32] + beta[lane + 32]; b = fmaxf(b, 0.f);
    float d = a * W2[lane] + b * W2[lane + 32];
    #pragma unroll
    for (int o = 16; o > 0; o >>= 1) d += __shfl_down_sync(0xffffffffu, d, o);
    if (lane == 0) g_h2[e] = d;
}
__global__ void k_agg2() {
    int n = blockIdx.x * blockDim.x + threadIdx.x;
    if (n >= NN) return;
    int o = g_incoff[n], L = g_ndeg[n];
    float s = 0.f;
    for (int j = 0; j < L; j++) { int e = g_inc[o + j]; s += g_dinv[e] * g_h2[e]; }
    g_agg2[n] = s;
}
__global__ void k_score(const float* __restrict__ b2) {   /* score + radix hist pass 0 */
    int e = blockIdx.x * blockDim.x + threadIdx.x;
    if (e >= MAXE || e >= g_E) return;
    float di = g_dinv[e];
    float z = di * (g_agg2[g_csrc[e]] + g_agg2[g_cdst[e]]) - di * di * g_h2[e] + b2[0];
    float s = 1.0f / (1.0f + expf(-z));
    g_score[e] = s;
    unsigned kk = __float_as_uint(s);
    g_keyv[e] = kk;
    atomicAdd(&g_hist[(kk >> 24) & 255], 1);
}

/* ------------------------------ stage 3: top-k radix select ------------------------------ */
__global__ void k_hist_sel(int shift, unsigned maskHi) {
    int e = blockIdx.x * blockDim.x + threadIdx.x;
    if (e >= MAXE || e >= g_E) return;
    unsigned kk = g_keyv[e];
    if ((kk & maskHi) == (g_prefix & maskHi))
        atomicAdd(&g_hist[(kk >> shift) & 255], 1);
}
__global__ void k_pick(int shift) {
    if (threadIdx.x != 0 || blockIdx.x != 0) return;
    int krem = g_krem;
    int cum = 0, chosen = 0;
    for (int b = 255; b >= 0; b--) {
        int h = g_hist[b];
        if (cum + h >= krem) { chosen = b; break; }
        cum += h;
    }
    g_prefix |= ((unsigned)chosen) << shift;
    g_krem = krem - cum;
    g_c1 += cum;
    for (int b = 0; b < 256; b++) g_hist[b] = 0;
}
/* select strictly-greater keys directly (atomicMin cluster), count eq per block */
__global__ void k_sel1() {
    int i = blockIdx.x * blockDim.x + threadIdx.x;
    unsigned T = g_prefix;
    int E = g_E;
    int eq = 0;
    if (i < E) {
        unsigned kk = g_keyv[i];
        if (kk > T) {
            unsigned long long pk = (((unsigned long long)kk) << 32) | (unsigned)(0xFFFFFFFFu - (unsigned)i);
            atomicMin(&g_packed[g_cdst[i]], pk);
        }
        eq = (kk == T) ? 1 : 0;
    }
    unsigned bal = __ballot_sync(0xffffffffu, eq);
    __shared__ int ws[8];
    int lane = threadIdx.x & 31, wid = threadIdx.x >> 5;
    if (lane == 0) ws[wid] = __popc(bal);
    __syncthreads();
    if (threadIdx.x == 0) {
        int s = 0;
        #pragma unroll
        for (int k = 0; k < 8; k++) s += ws[k];
        g_bcnt[blockIdx.x] = s;
    }
}
/* eq-keys: global index-ordered rank < krem -> selected (jax tie semantics) */
__global__ void k_sel3() {
    int i = blockIdx.x * blockDim.x + threadIdx.x;
    unsigned T = g_prefix;
    int E = g_E;
    int eq = (i < E && g_keyv[i] == T) ? 1 : 0;
    unsigned bal = __ballot_sync(0xffffffffu, eq);
    int lane = threadIdx.x & 31, wid = threadIdx.x >> 5;
    __shared__ int ws[8];
    if (lane == 0) ws[wid] = __popc(bal);
    __syncthreads();
    int pre = 0;
    for (int k = 0; k < wid; k++) pre += ws[k];
    int lexcl = pre + __popc(bal & ((1u << lane) - 1u));
    if (eq) {
        int rank = g_boff[blockIdx.x] + lexcl;
        if (rank < g_krem) {
            unsigned long long pk = (((unsigned long long)T) << 32) | (unsigned)(0xFFFFFFFFu - (unsigned)i);
            atomicMin(&g_packed[g_cdst[i]], pk);
        }
    }
}

/* ------------------------------ stage 4: clustering ------------------------------ */
__global__ void k_n2c() {
    int n = blockIdx.x * blockDim.x + threadIdx.x;
    if (n >= NN) return;
    unsigned long long pk = g_packed[n];
    int v;
    if (pk != ~0ull) {
        unsigned e = 0xFFFFFFFFu - (unsigned)(pk & 0xFFFFFFFFull);
        v = g_csrc[e];
    } else v = n;
    g_n2c[n] = v;
    g_flag[v] = 1;
}
__global__ void k_maps() {   /* maps + pool histogram */
    int n = blockIdx.x * blockDim.x + threadIdx.x;
    if (n >= NN) return;
    if (g_flag[n]) g_uniq[g_rankv[n]] = n;
    int m = g_rankv[g_n2c[n]];
    g_ni[n] = m;
    atomicAdd(&g_pcnt[m], 1);
}

/* ------------------------------ stage 5: node pooling ------------------------------ */
__global__ void k_pscat() {
    int n = blockIdx.x * blockDim.x + threadIdx.x;
    if (n >= NN) return;
    int m = g_ni[n];
    int pos = g_poff[m] + atomicAdd(&g_fill3[m], 1);
    g_pnode[pos] = n;
}
__global__ void k_xpool(const float* __restrict__ x, float* __restrict__ out) {
    int idx = blockIdx.x * blockDim.x + threadIdx.x;
    if (idx >= NN * 128) return;
    int m = idx >> 7, c = idx & 127;
    if (m >= g_M) return;
    int o = g_poff[m], L = g_pcnt[m];
    float s = 0.f;
    for (int j = 0; j < L; j++) s += x[g_pnode[o + j] * 128 + c];
    out[m * 128 + c] = s / (float)L;
}

/* ------------------------------ stage 6: pooled edges (bitmask dedup) ------------------------------ */
__global__ void k_ehist(const int* __restrict__ ei) {
    int i = blockIdx.x * blockDim.x + threadIdx.x;
    if (i >= ED) return;
    int ns = g_ni[ei[i]], nd = g_ni[ei[ED + i]];
    if (ns != nd) atomicAdd(&g_ecnt[ns], 1);
}
__global__ void k_escat(const int* __restrict__ ei) {
    int i = blockIdx.x * blockDim.x + threadIdx.x;
    if (i >= ED) return;
    int ns = g_ni[ei[i]], nd = g_ni[ei[ED + i]];
    if (ns != nd) {
        int pos = g_eoffA[ns] + atomicAdd(&g_fill4[ns], 1);
        g_bucket[pos] = nd;
    }
}
__global__ void k_eucount() {   /* one block per cluster: unique neighbor count via bitmask */
    int m = blockIdx.x;
    if (m >= g_M) return;
    __shared__ unsigned mask[MW];
    __shared__ int red[256];
    int t = threadIdx.x;
    for (int w = t; w < MW; w += 256) mask[w] = 0u;
    __syncthreads();
    int o = g_eoffA[m], L = g_ecnt[m];
    for (int j = t; j < L; j += 256) {
        int nd = g_bucket[o + j];
        atomicOr(&mask[nd >> 5], 1u << (nd & 31));
    }
    __syncthreads();
    int s = 0;
    for (int w = t; w < MW; w += 256) s += __popc(mask[w]);
    red[t] = s;
    __syncthreads();
    for (int st = 128; st > 0; st >>= 1) { if (t < st) red[t] += red[t + st]; __syncthreads(); }
    if (t == 0) g_ucnt[m] = red[0];
}
__global__ void k_eemit(float* __restrict__ out) {   /* emit sorted unique neighbors */
    int m = blockIdx.x;
    if (m >= g_M) return;
    __shared__ unsigned mask[MW];
    __shared__ int wsum[8];
    int t = threadIdx.x;
    for (int w = t; w < MW; w += 256) mask[w] = 0u;
    __syncthreads();
    int o = g_eoffA[m], L = g_ecnt[m];
    for (int j = t; j < L; j += 256) {
        int nd = g_bucket[o + j];
        atomicOr(&mask[nd >> 5], 1u << (nd & 31));
    }
    __syncthreads();
    int w0 = t * 3;
    int ls = 0;
    #pragma unroll
    for (int k = 0; k < 3; k++) { int w = w0 + k; if (w < MW) ls += __popc(mask[w]); }
    int lane = t & 31, wid = t >> 5;
    int x = ls;
    #pragma unroll
    for (int off = 1; off < 32; off <<= 1) { int y = __shfl_up_sync(0xffffffffu, x, off); if (lane >= off) x += y; }
    if (lane == 31) wsum[wid] = x;
    __syncthreads();
    int pre = 0;
    for (int k = 0; k < wid; k++) pre += wsum[k];
    int off2 = pre + x - ls;
    long base = 128L * g_M;
    int ob = g_eoffB[m], P = g_P;
    #pragma unroll
    for (int k = 0; k < 3; k++) {
        int w = w0 + k; if (w >= MW) break;
        unsigned mw = mask[w];
        while (mw) {
            int b = __ffs(mw) - 1;
            out[base + ob + off2] = (float)m;
            out[base + (long)P + ob + off2] = (float)(w * 32 + b);
            off2++;
            mw &= mw - 1u;
        }
    }
}

/* ------------------------------ stage 7: tail outputs ------------------------------ */
__global__ void k_tail(const int* __restrict__ batch, float* __restrict__ out) {
    int i = blockIdx.x * blockDim.x + threadIdx.x;
    if (i >= MAXE) return;
    int E = g_E, M = g_M, P = g_P;
    long base = 128L * M + 2L * P;
    if (i < M) out[base + i] = (float)batch[g_uniq[i]];
    if (i < E) out[base + M + i] = g_score[i];
    if (i < NN) out[base + M + E + i] = (float)g_ni[i];
}

/* ------------------------------ launch ------------------------------ */
extern "C" void kernel_launch(void* const* d_in, const int* in_sizes, int n_in,
                              void* d_out, int out_size) {
    const float* x      = (const float*)d_in[0];
    const float* W1     = (const float*)d_in[1];
    const float* b1     = (const float*)d_in[2];
    const float* gamma1 = (const float*)d_in[3];
    const float* beta1  = (const float*)d_in[4];
    const float* W2     = (const float*)d_in[5];
    const float* b2     = (const float*)d_in[6];
    const int*   ei     = (const int*)d_in[7];
    const int*   batch  = (const int*)d_in[8];
    float* out = (float*)d_out;

    void* p;
    int *cnt, *offA, *offB, *bucket, *ndeg, *incoff, *inc, *flag, *rankv;
    int *pcnt, *poff, *pnode, *ecnt, *eoffA, *ucnt, *eoffB, *bcnt, *boff;
    cudaGetSymbolAddress(&p, g_cnt);    cnt    = (int*)p;
    cudaGetSymbolAddress(&p, g_offA);   offA   = (int*)p;
    cudaGetSymbolAddress(&p, g_offB);   offB   = (int*)p;
    cudaGetSymbolAddress(&p, g_bucket); bucket = (int*)p;
    cudaGetSymbolAddress(&p, g_ndeg);   ndeg   = (int*)p;
    cudaGetSymbolAddress(&p, g_incoff); incoff = (int*)p;
    cudaGetSymbolAddress(&p, g_inc);    inc    = (int*)p;
    cudaGetSymbolAddress(&p, g_flag);   flag   = (int*)p;
    cudaGetSymbolAddress(&p, g_rankv);  rankv  = (int*)p;
    cudaGetSymbolAddress(&p, g_pcnt);   pcnt   = (int*)p;
    cudaGetSymbolAddress(&p, g_poff);   poff   = (int*)p;
    cudaGetSymbolAddress(&p, g_pnode);  pnode  = (int*)p;
    cudaGetSymbolAddress(&p, g_ecnt);   ecnt   = (int*)p;
    cudaGetSymbolAddress(&p, g_eoffA);  eoffA  = (int*)p;
    cudaGetSymbolAddress(&p, g_ucnt);   ucnt   = (int*)p;
    cudaGetSymbolAddress(&p, g_eoffB);  eoffB  = (int*)p;
    cudaGetSymbolAddress(&p, g_bcnt);   bcnt   = (int*)p;
    cudaGetSymbolAddress(&p, g_boff);   boff   = (int*)p;

    const int B = 256;
    const int gN  = (NN + B - 1) / B;
    const int gED = (ED + B - 1) / B;
    const int gE  = (MAXE + B - 1) / B;
    const int gEC = (MAXE * 64 + B - 1) / B;
    const int gNC = (NN * 64 + B - 1) / B;

    k_init<<<gN, B>>>();

    /* stage 1: clean edges + incidence CSR */
    k_hist_u<<<gED, B>>>(ei);
    k_scan<<<1, 1024>>>(cnt, offA, NN, 0);
    k_scatter_u<<<gED, B>>>(ei);
    k_sort<<<gN, B>>>(bucket, offA, cnt, NN, 1);
    k_scan<<<1, 1024>>>(cnt, offB, NN, 1);          /* -> g_E */
    k_compact<<<gN, B>>>();
    k_scan<<<1, 1024>>>(ndeg, incoff, NN, 0);
    k_incscat<<<gE, B>>>();
    k_sort<<<gN, B>>>(inc, incoff, ndeg, NN, 0);

    /* stage 2: features / GCN / BN / scores */
    k_gemm<<<NN / 4, B>>>(x, W1);
    k_edge_h<<<gEC, B>>>();
    k_aggN<<<gNC, B>>>();
    k_conv1<<<gEC, B>>>(b1);
    k_bn_part<<<BN_BLOCKS, B>>>();
    k_bn_final<<<1, 64>>>();
    k_bnrelu_dot<<<(MAXE * 32 + B - 1) / B, B>>>(gamma1, beta1, W2);
    k_agg2<<<gN, B>>>();
    k_score<<<gE, B>>>(b2);

    /* stage 3: top-k radix select (hist pass 0 fused into k_score) */
    k_pick<<<1, 1>>>(24);
    for (int pidx = 1; pidx < 4; pidx++) {
        int shift = 24 - 8 * pidx;
        unsigned maskHi = 0xFFFFFFFFu << (shift + 8);
        k_hist_sel<<<gE, B>>>(shift, maskHi);
        k_pick<<<1, 1>>>(shift);
    }
    k_sel1<<<SELB, B>>>();
    k_scan<<<1, 1024>>>(bcnt, boff, SELB, 0);
    k_sel3<<<SELB, B>>>();

    /* stage 4: clustering */
    k_n2c<<<gN, B>>>();
    k_scan<<<1, 1024>>>(flag, rankv, NN, 2);        /* -> g_M */
    k_maps<<<gN, B>>>();

    /* stage 5: node pooling */
    k_scan<<<1, 1024>>>(pcnt, poff, NN, 0);
    k_pscat<<<gN, B>>>();
    k_sort<<<gN, B>>>(pnode, poff, pcnt, NN, 0);
    k_xpool<<<(NN * 128 + B - 1) / B, B>>>(x, out);

    /* stage 6: pooled edges */
    k_ehist<<<gED, B>>>(ei);
    k_scan<<<1, 1024>>>(ecnt, eoffA, NN, 0);
    k_escat<<<gED, B>>>(ei);
    k_eucount<<<NN, B>>>();
    k_scan<<<1, 1024>>>(ucnt, eoffB, NN, 3);        /* -> g_P */
    k_eemit<<<NN, B>>>(out);

    /* stage 7: tail */
    k_tail<<<gE, B>>>(batch, out);

    (void)in_sizes; (void)n_in; (void)out_size;
}

// round 5
// speedup vs baseline: 1.2706x; 1.0612x over previous
#include <cuda_runtime.h>
#include <math.h>

#define NN 20000
#define ED 160000
#define MAXE 160000
#define G 296
#define T 256
#define GT (G * T)
#define MW 625   /* bitmask words for NN bits */

/* ------------------------------ scratch ------------------------------ */
__device__ int g_bar_cnt = 0;
__device__ int g_bar_gen = 0;

__device__ int g_cnt[NN], g_fill1[NN], g_fill2[NN], g_fill3[NN], g_fill4[NN];
__device__ int g_offA[NN], g_offB[NN];
__device__ int g_bucket[ED];
__device__ int g_csrc[MAXE], g_cdst[MAXE];
__device__ int g_ndeg[NN], g_incoff[NN];
__device__ int g_inc[2 * MAXE];
__device__ float g_dinv[MAXE];
__device__ float g_xW[NN * 64];
__device__ float g_aggN[NN * 64];
__device__ double g_p1[G * 64], g_p2[G * 64];
__device__ float g_mu[64], g_istd[64];
__device__ float g_h2[MAXE], g_agg2[NN], g_score[MAXE];
__device__ unsigned g_keyv[MAXE];
__device__ int g_hist[256];
__device__ unsigned long long g_packed[NN];
__device__ int g_bcnt[G], g_boff[G];
__device__ int g_n2c[NN], g_flag[NN], g_rankv[NN], g_uniq[NN], g_ni[NN];
__device__ int g_pcnt[NN], g_poff[NN], g_pnode[NN];
__device__ int g_ecnt[NN], g_eoffA[NN], g_ucnt[NN], g_eoffB[NN];
__device__ int g_E, g_M, g_P, g_krem;
__device__ unsigned g_prefix;

/* ------------------------------ grid barrier ------------------------------ */
__device__ __forceinline__ void gsync() {
    __syncthreads();
    if (threadIdx.x == 0) {
        __threadfence();
        int gen = atomicAdd(&g_bar_gen, 0);
        if (atomicAdd(&g_bar_cnt, 1) == G - 1) {
            atomicExch(&g_bar_cnt, 0);
            __threadfence();
            atomicAdd(&g_bar_gen, 1);
        } else {
            while (atomicAdd(&g_bar_gen, 0) == gen) __nanosleep(64);
        }
    }
    __syncthreads();
}

/* ---------------- block-0 exclusive scan (all threads of block 0) ---------------- */
__device__ void scan_b0(const int* in, int* out, int n, int total_code, char* SMEM) {
    if (blockIdx.x == 0) {
        int* ssum = (int*)SMEM;
        int t = threadIdx.x;
        int per = (n + T - 1) / T;
        int lo = t * per, hi = lo + per; if (hi > n) hi = n; if (lo > n) lo = n;
        int s = 0;
        for (int i = lo; i < hi; i++) s += __ldcg(in + i);
        ssum[t] = s;
        __syncthreads();
        if (t == 0) {
            int acc = 0;
            for (int i = 0; i < T; i++) { int v = ssum[i]; ssum[i] = acc; acc += v; }
            if (total_code == 1) g_E = acc;
            else if (total_code == 2) g_M = acc;
            else if (total_code == 3) g_P = acc;
        }
        __syncthreads();
        int acc = ssum[t];
        for (int i = lo; i < hi; i++) { int v = __ldcg(in + i); out[i] = acc; acc += v; }
    }
}

/* ---------------- radix-select helpers ---------------- */
__device__ void hist_phase(int shift, unsigned maskHi) {
    int E = g_E;
    unsigned P = __ldcg(&g_prefix);
    for (int e = blockIdx.x * T + threadIdx.x; e < E; e += GT) {
        unsigned kk = g_keyv[e];
        if ((kk & maskHi) == (P & maskHi)) atomicAdd(&g_hist[(kk >> shift) & 255], 1);
    }
}
__device__ void pick_b0(int shift, char* SMEM) {
    if (blockIdx.x == 0) {
        int* sh = (int*)SMEM;
        int t = threadIdx.x;
        sh[t] = __ldcg(&g_hist[t]);
        __syncthreads();
        if (t == 0) {
            int krem = __ldcg(&g_krem);
            int cum = 0, chosen = 0;
            for (int b = 255; b >= 0; b--) {
                int h = sh[b];
                if (cum + h >= krem) { chosen = b; break; }
                cum += h;
            }
            g_prefix = __ldcg(&g_prefix) | (((unsigned)chosen) << shift);
            g_krem = krem - cum;
        }
        __syncthreads();
        g_hist[t] = 0;
    }
}

/* ------------------------------ megakernel ------------------------------ */
extern "C" __global__ void __launch_bounds__(T, 3)
mega(const float* __restrict__ x, const float* __restrict__ W1, const float* __restrict__ b1,
     const float* __restrict__ gamma1, const float* __restrict__ beta1,
     const float* __restrict__ W2, const float* __restrict__ b2,
     const int* __restrict__ ei, const int* __restrict__ batch,
     float* __restrict__ out) {
    __shared__ __align__(16) char SMEM[40960];
    const int t = threadIdx.x;
    const int b = blockIdx.x;
    const int gtid = b * T + t;

    /* ---- ph0: init ---- */
    for (int i = gtid; i < NN; i += GT) {
        g_cnt[i] = 0; g_fill1[i] = 0; g_fill2[i] = 0; g_fill3[i] = 0; g_fill4[i] = 0;
        g_ndeg[i] = 0; g_ecnt[i] = 0; g_pcnt[i] = 0; g_flag[i] = 0; g_ucnt[i] = 0;
        g_packed[i] = ~0ull;
    }
    if (gtid < 256) g_hist[gtid] = 0;
    gsync();

    /* ---- ph1: histogram of raw undirected edges by src ---- */
    for (int i = gtid; i < ED; i += GT) {
        int s = ei[i], d = ei[ED + i];
        if (s < d) atomicAdd(&g_cnt[s], 1);
    }
    gsync();

    /* ---- ph2: scan cnt -> offA ---- */
    scan_b0(g_cnt, g_offA, NN, 0, SMEM);
    gsync();

    /* ---- ph3: scatter to buckets ---- */
    for (int i = gtid; i < ED; i += GT) {
        int s = ei[i], d = ei[ED + i];
        if (s < d) {
            int pos = g_offA[s] + atomicAdd(&g_fill1[s], 1);
            g_bucket[pos] = d;
        }
    }
    gsync();

    /* ---- ph4: per-node sort + dedup ---- */
    for (int u = gtid; u < NN; u += GT) {
        int o = g_offA[u], L = g_cnt[u];
        for (int i = 1; i < L; i++) {
            int key = g_bucket[o + i]; int j = i - 1;
            while (j >= 0 && g_bucket[o + j] > key) { g_bucket[o + j + 1] = g_bucket[o + j]; j--; }
            g_bucket[o + j + 1] = key;
        }
        int m = 0;
        for (int i = 0; i < L; i++) {
            int v = g_bucket[o + i];
            if (m == 0 || v != g_bucket[o + m - 1]) g_bucket[o + m++] = v;
        }
        g_cnt[u] = m;
    }
    gsync();

    /* ---- ph5: scan deduped counts -> offB, total E ---- */
    scan_b0(g_cnt, g_offB, NN, 1, SMEM);
    gsync();

    /* ---- ph6: compact clean edge list + node degrees ---- */
    for (int u = gtid; u < NN; u += GT) {
        int L = g_cnt[u], ob = g_offB[u], oa = g_offA[u];
        for (int j = 0; j < L; j++) {
            int d = g_bucket[oa + j];
            g_csrc[ob + j] = u; g_cdst[ob + j] = d;
            atomicAdd(&g_ndeg[d], 1);
        }
        if (L) atomicAdd(&g_ndeg[u], L);
    }
    gsync();

    /* ---- ph7: scan ndeg -> incoff ---- */
    scan_b0(g_ndeg, g_incoff, NN, 0, SMEM);
    gsync();

    /* ---- ph8: incidence scatter + dinv ---- */
    {
        int E = g_E;
        for (int e = gtid; e < E; e += GT) {
            int u = g_csrc[e], v = g_cdst[e];
            int p1 = g_incoff[u] + atomicAdd(&g_fill2[u], 1); g_inc[p1] = e;
            int p2 = g_incoff[v] + atomicAdd(&g_fill2[v], 1); g_inc[p2] = e;
            int deg = g_ndeg[u] + g_ndeg[v] - 1;
            if (deg < 1) deg = 1;
            g_dinv[e] = 1.0f / sqrtf((float)deg);
        }
    }
    gsync();

    /* ---- ph9: sort incidence lists (deterministic sum order) ---- */
    for (int u = gtid; u < NN; u += GT) {
        int o = g_incoff[u], L = g_ndeg[u];
        for (int i = 1; i < L; i++) {
            int key = g_inc[o + i]; int j = i - 1;
            while (j >= 0 && g_inc[o + j] > key) { g_inc[o + j + 1] = g_inc[o + j]; j--; }
            g_inc[o + j + 1] = key;
        }
    }
    gsync();

    /* ---- ph10: xW = x @ W1  (row groups of 4) ---- */
    {
        float* sW = (float*)SMEM;                 /* 128*64 = 32KB */
        float* sx = (float*)(SMEM + 32768);       /* 4*128  = 2KB  */
        for (int i = t; i < 128 * 64; i += T) sW[i] = W1[i];
        __syncthreads();
        for (int grp = b; grp < NN / 4; grp += G) {
            int r0 = grp * 4;
            for (int i = t; i < 4 * 128; i += T) {
                int rr = i >> 7, kk = i & 127;
                sx[rr * 128 + kk] = x[(r0 + rr) * 128 + kk];
            }
            __syncthreads();
            int c = t & 63, rr = t >> 6;
            float acc = 0.f;
            #pragma unroll
            for (int k2 = 0; k2 < 128; k2++) acc += sx[rr * 128 + k2] * sW[k2 * 64 + c];
            g_xW[(r0 + rr) * 64 + c] = acc;
            __syncthreads();
        }
    }
    gsync();

    /* ---- ph11: aggN[n,c] = sum_{e inc n} dinv_e * 0.5*(xW[u]+xW[v]) ---- */
    for (int idx = gtid; idx < NN * 64; idx += GT) {
        int n = idx >> 6, c = idx & 63;
        int o = g_incoff[n], L = g_ndeg[n];
        float s = 0.f;
        for (int j = 0; j < L; j++) {
            int e = g_inc[o + j];
            float h = 0.5f * (g_xW[g_csrc[e] * 64 + c] + g_xW[g_cdst[e] * 64 + c]);
            s += g_dinv[e] * h;
        }
        g_aggN[idx] = s;
    }
    gsync();

    /* ---- ph12: BN stats over conv1 output (recomputed on the fly) ---- */
    {
        int E = g_E;
        double s = 0.0, s2 = 0.0;
        float bc = b1[t & 63];
        for (int idx = gtid; idx < E * 64; idx += GT) {
            int e = idx >> 6, c = idx & 63;
            int u = g_csrc[e], v = g_cdst[e];
            float di = g_dinv[e];
            float h = 0.5f * (g_xW[u * 64 + c] + g_xW[v * 64 + c]);
            float z = di * (g_aggN[u * 64 + c] + g_aggN[v * 64 + c]) - di * di * h + bc;
            double zd = (double)z;
            s += zd; s2 += zd * zd;
        }
        double* sA = (double*)SMEM;
        double* sB = (double*)(SMEM + 2048);
        sA[t] = s; sB[t] = s2;
        __syncthreads();
        if (t < 64) {
            g_p1[b * 64 + t] = sA[t] + sA[t + 64] + sA[t + 128] + sA[t + 192];
            g_p2[b * 64 + t] = sB[t] + sB[t + 64] + sB[t + 128] + sB[t + 192];
        }
    }
    gsync();

    /* ---- ph13: BN finalize + top-k init ---- */
    if (b == 0 && t < 64) {
        double s = 0.0, s2 = 0.0;
        for (int bb = 0; bb < G; bb++) { s += g_p1[bb * 64 + t]; s2 += g_p2[bb * 64 + t]; }
        double Ed = (double)g_E;
        double mu = s / Ed;
        double var = s2 / Ed - mu * mu;
        g_mu[t] = (float)mu;
        g_istd[t] = (float)(1.0 / sqrt(var + 1e-5));
        if (t == 0) {
            int E = g_E;
            int k = E / 2;
            if (k > NN / 2) k = NN / 2;
            if (k < 1) k = 1;
            g_krem = k; g_prefix = 0u;
        }
    }
    gsync();

    /* ---- ph14: BN+ReLU+dot -> h2 (conv1 recomputed) ---- */
    {
        int E = g_E;
        int lane = t & 31;
        float ga0 = gamma1[lane],      be0 = beta1[lane],      w20 = W2[lane],      bb0 = b1[lane];
        float ga1 = gamma1[lane + 32], be1 = beta1[lane + 32], w21 = W2[lane + 32], bb1 = b1[lane + 32];
        float mu0 = g_mu[lane], is0 = g_istd[lane], mu1 = g_mu[lane + 32], is1 = g_istd[lane + 32];
        for (int gt = gtid; gt < E * 32; gt += GT) {
            int e = gt >> 5;
            int u = g_csrc[e], v = g_cdst[e];
            float di = g_dinv[e], di2 = di * di;
            float h0 = 0.5f * (g_xW[u * 64 + lane] + g_xW[v * 64 + lane]);
            float z0 = di * (g_aggN[u * 64 + lane] + g_aggN[v * 64 + lane]) - di2 * h0 + bb0;
            float h1 = 0.5f * (g_xW[u * 64 + 32 + lane] + g_xW[v * 64 + 32 + lane]);
            float z1 = di * (g_aggN[u * 64 + 32 + lane] + g_aggN[v * 64 + 32 + lane]) - di2 * h1 + bb1;
            float a0 = fmaxf(ga0 * (z0 - mu0) * is0 + be0, 0.f);
            float a1 = fmaxf(ga1 * (z1 - mu1) * is1 + be1, 0.f);
            float d = a0 * w20 + a1 * w21;
            #pragma unroll
            for (int o = 16; o > 0; o >>= 1) d += __shfl_down_sync(0xffffffffu, d, o);
            if (lane == 0) g_h2[e] = d;
        }
    }
    gsync();

    /* ---- ph15: agg2 per node ---- */
    for (int n = gtid; n < NN; n += GT) {
        int o = g_incoff[n], L = g_ndeg[n];
        float s = 0.f;
        for (int j = 0; j < L; j++) { int e = g_inc[o + j]; s += g_dinv[e] * g_h2[e]; }
        g_agg2[n] = s;
    }
    gsync();

    /* ---- ph16: scores + radix hist pass 0 ---- */
    {
        int E = g_E;
        float bias2 = b2[0];
        for (int e = gtid; e < E; e += GT) {
            float di = g_dinv[e];
            float z = di * (g_agg2[g_csrc[e]] + g_agg2[g_cdst[e]]) - di * di * g_h2[e] + bias2;
            float s = 1.0f / (1.0f + expf(-z));
            g_score[e] = s;
            unsigned kk = __float_as_uint(s);
            g_keyv[e] = kk;
            atomicAdd(&g_hist[(kk >> 24) & 255], 1);
        }
    }
    gsync();

    /* ---- ph17..23: radix select passes ---- */
    pick_b0(24, SMEM); gsync();
    hist_phase(16, 0xFF000000u); gsync();
    pick_b0(16, SMEM); gsync();
    hist_phase(8, 0xFFFF0000u); gsync();
    pick_b0(8, SMEM); gsync();
    hist_phase(0, 0xFFFFFF00u); gsync();
    pick_b0(0, SMEM); gsync();

    /* ---- ph24: strictly-greater -> atomicMin cluster; count eq per block ---- */
    {
        int E = g_E;
        unsigned Tp = __ldcg(&g_prefix);
        int cb = (E + G - 1) / G;
        int lo = b * cb, hi = lo + cb; if (hi > E) hi = E;
        int cnt = 0;
        for (int base = lo; base < hi; base += T) {
            int i = base + t;
            if (i < hi) {
                unsigned kk = g_keyv[i];
                if (kk > Tp) {
                    unsigned long long pk = (((unsigned long long)kk) << 32) | (unsigned)(0xFFFFFFFFu - (unsigned)i);
                    atomicMin(&g_packed[g_cdst[i]], pk);
                }
                if (kk == Tp) cnt++;
            }
        }
        int* red = (int*)SMEM;
        red[t] = cnt;
        __syncthreads();
        for (int st = 128; st > 0; st >>= 1) { if (t < st) red[t] += red[t + st]; __syncthreads(); }
        if (t == 0) g_bcnt[b] = red[0];
    }
    gsync();

    /* ---- ph25: scan bcnt -> boff ---- */
    scan_b0(g_bcnt, g_boff, G, 0, SMEM);
    gsync();

    /* ---- ph26: eq keys, index-ordered rank < krem -> select ---- */
    {
        int E = g_E;
        unsigned Tp = __ldcg(&g_prefix);
        int krem = __ldcg(&g_krem);
        int cb = (E + G - 1) / G;
        int lo = b * cb, hi = lo + cb; if (hi > E) hi = E;
        int* ws = (int*)SMEM;          /* 8 */
        int* scarry = (int*)SMEM + 16;
        if (t == 0) *scarry = 0;
        __syncthreads();
        int lane = t & 31, wid = t >> 5;
        for (int base = lo; base < hi; base += T) {
            int i = base + t;
            int eq = (i < hi && g_keyv[i] == Tp) ? 1 : 0;
            unsigned bal = __ballot_sync(0xffffffffu, eq);
            if (lane == 0) ws[wid] = __popc(bal);
            __syncthreads();
            int pre = 0;
            for (int k = 0; k < wid; k++) pre += ws[k];
            int lexcl = pre + __popc(bal & ((1u << lane) - 1u));
            if (eq) {
                int rank = g_boff[b] + *scarry + lexcl;
                if (rank < krem) {
                    unsigned long long pk = (((unsigned long long)Tp) << 32) | (unsigned)(0xFFFFFFFFu - (unsigned)i);
                    atomicMin(&g_packed[g_cdst[i]], pk);
                }
            }
            __syncthreads();
            if (t == 0) {
                int tot = 0;
                #pragma unroll
                for (int k = 0; k < 8; k++) tot += ws[k];
                *scarry += tot;
            }
            __syncthreads();
        }
    }
    gsync();

    /* ---- ph27: node -> cluster label ---- */
    for (int n = gtid; n < NN; n += GT) {
        unsigned long long pk = g_packed[n];
        int v;
        if (pk != ~0ull) {
            unsigned e = 0xFFFFFFFFu - (unsigned)(pk & 0xFFFFFFFFull);
            v = g_csrc[e];
        } else v = n;
        g_n2c[n] = v;
        g_flag[v] = 1;
    }
    gsync();

    /* ---- ph28: scan flag -> rankv, total M ---- */
    scan_b0(g_flag, g_rankv, NN, 2, SMEM);
    gsync();

    /* ---- ph29: maps + pool counts ---- */
    for (int n = gtid; n < NN; n += GT) {
        if (g_flag[n]) g_uniq[g_rankv[n]] = n;
        int m = g_rankv[g_n2c[n]];
        g_ni[n] = m;
        atomicAdd(&g_pcnt[m], 1);
    }
    gsync();

    /* ---- ph30: scan pcnt -> poff ---- */
    scan_b0(g_pcnt, g_poff, NN, 0, SMEM);
    gsync();

    /* ---- ph31: scatter members ---- */
    for (int n = gtid; n < NN; n += GT) {
        int m = g_ni[n];
        int pos = g_poff[m] + atomicAdd(&g_fill3[m], 1);
        g_pnode[pos] = n;
    }
    gsync();

    /* ---- ph32: sort member lists (deterministic sum order) ---- */
    {
        int M = g_M;
        for (int m = gtid; m < M; m += GT) {
            int o = g_poff[m], L = g_pcnt[m];
            for (int i = 1; i < L; i++) {
                int key = g_pnode[o + i]; int j = i - 1;
                while (j >= 0 && g_pnode[o + j] > key) { g_pnode[o + j + 1] = g_pnode[o + j]; j--; }
                g_pnode[o + j + 1] = key;
            }
        }
    }
    gsync();

    /* ---- ph33: x_pool ---- */
    {
        int M = g_M;
        for (int idx = gtid; idx < M * 128; idx += GT) {
            int m = idx >> 7, c = idx & 127;
            int o = g_poff[m], L = g_pcnt[m];
            float s = 0.f;
            for (int j = 0; j < L; j++) s += x[g_pnode[o + j] * 128 + c];
            out[m * 128 + c] = s / (float)L;
        }
    }
    gsync();

    /* ---- ph34: pooled-edge histogram ---- */
    for (int i = gtid; i < ED; i += GT) {
        int ns = g_ni[ei[i]], nd = g_ni[ei[ED + i]];
        if (ns != nd) atomicAdd(&g_ecnt[ns], 1);
    }
    gsync();

    /* ---- ph35: scan ecnt -> eoffA ---- */
    scan_b0(g_ecnt, g_eoffA, NN, 0, SMEM);
    gsync();

    /* ---- ph36: scatter pooled edges ---- */
    for (int i = gtid; i < ED; i += GT) {
        int ns = g_ni[ei[i]], nd = g_ni[ei[ED + i]];
        if (ns != nd) {
            int pos = g_eoffA[ns] + atomicAdd(&g_fill4[ns], 1);
            g_bucket[pos] = nd;
        }
    }
    gsync();

    /* ---- ph37: unique neighbor counts via bitmask ---- */
    {
        int M = g_M;
        unsigned* mask = (unsigned*)SMEM;        /* MW words */
        int* red = (int*)(SMEM + 2560);          /* 256 ints */
        for (int m = b; m < M; m += G) {
            __syncthreads();
            for (int w = t; w < MW; w += T) mask[w] = 0u;
            __syncthreads();
            int o = g_eoffA[m], L = g_ecnt[m];
            for (int j = t; j < L; j += T) {
                int nd = __ldcg(&g_bucket[o + j]);
                atomicOr(&mask[nd >> 5], 1u << (nd & 31));
            }
            __syncthreads();
            int s = 0;
            for (int w = t; w < MW; w += T) s += __popc(mask[w]);
            red[t] = s;
            __syncthreads();
            for (int st = 128; st > 0; st >>= 1) { if (t < st) red[t] += red[t + st]; __syncthreads(); }
            if (t == 0) g_ucnt[m] = red[0];
        }
    }
    gsync();

    /* ---- ph38: scan ucnt -> eoffB, total P ---- */
    scan_b0(g_ucnt, g_eoffB, NN, 3, SMEM);
    gsync();

    /* ---- ph39: emit sorted unique pooled edges ---- */
    {
        int M = g_M;
        long base = 128L * M;
        int P = g_P;
        unsigned* mask = (unsigned*)SMEM;
        int* wsum = (int*)(SMEM + 2560);
        for (int m = b; m < M; m += G) {
            __syncthreads();
            for (int w = t; w < MW; w += T) mask[w] = 0u;
            __syncthreads();
            int o = g_eoffA[m], L = g_ecnt[m];
            for (int j = t; j < L; j += T) {
                int nd = __ldcg(&g_bucket[o + j]);
                atomicOr(&mask[nd >> 5], 1u << (nd & 31));
            }
            __syncthreads();
            int w0 = t * 3;
            int ls = 0;
            #pragma unroll
            for (int k = 0; k < 3; k++) { int w = w0 + k; if (w < MW) ls += __popc(mask[w]); }
            int lane = t & 31, wid = t >> 5;
            int xx = ls;
            #pragma unroll
            for (int off = 1; off < 32; off <<= 1) { int y = __shfl_up_sync(0xffffffffu, xx, off); if (lane >= off) xx += y; }
            if (lane == 31) wsum[wid] = xx;
            __syncthreads();
            int pre = 0;
            for (int k = 0; k < wid; k++) pre += wsum[k];
            int off2 = pre + xx - ls;
            int ob = g_eoffB[m];
            #pragma unroll
            for (int k = 0; k < 3; k++) {
                int w = w0 + k; if (w >= MW) break;
                unsigned mw = mask[w];
                while (mw) {
                    int bit = __ffs(mw) - 1;
                    out[base + ob + off2] = (float)m;
                    out[base + (long)P + ob + off2] = (float)(w * 32 + bit);
                    off2++;
                    mw &= mw - 1u;
                }
            }
            __syncthreads();
        }
    }
    gsync();

    /* ---- ph40: tail outputs ---- */
    {
        int E = g_E, M = g_M, P = g_P;
        long base = 128L * M + 2L * P;
        for (int i = gtid; i < MAXE; i += GT) {
            if (i < M) out[base + i] = (float)batch[g_uniq[i]];
            if (i < E) out[base + M + i] = g_score[i];
            if (i < NN) out[base + M + E + i] = (float)g_ni[i];
        }
    }
}

/* ------------------------------ launch ------------------------------ */
extern "C" void kernel_launch(void* const* d_in, const int* in_sizes, int n_in,
                              void* d_out, int out_size) {
    const float* x      = (const float*)d_in[0];
    const float* W1     = (const float*)d_in[1];
    const float* b1     = (const float*)d_in[2];
    const float* gamma1 = (const float*)d_in[3];
    const float* beta1  = (const float*)d_in[4];
    const float* W2     = (const float*)d_in[5];
    const float* b2     = (const float*)d_in[6];
    const int*   ei     = (const int*)d_in[7];
    const int*   batch  = (const int*)d_in[8];
    float* out = (float*)d_out;

    mega<<<G, T>>>(x, W1, b1, gamma1, beta1, W2, b2, ei, batch, out);

    (void)in_sizes; (void)n_in; (void)out_size;
}

// round 6
// speedup vs baseline: 1.5048x; 1.1843x over previous
#include <cuda_runtime.h>
#include <math.h>

#define NN 20000
#define ED 160000
#define MAXE 160000
#define G 444
#define T 256
#define GT (G * T)
#define MW 625   /* bitmask words for NN bits */
#define SMALL_L 16

/* ------------------------------ scratch ------------------------------ */
__device__ int g_bar_cnt = 0;
__device__ int g_bar_gen = 0;

__device__ int g_cnt[NN], g_fill1[NN], g_fill2[NN], g_fill3[NN], g_fill4[NN];
__device__ int g_offA[NN], g_offB[NN];
__device__ int g_bucket[ED];
__device__ int g_csrc[MAXE], g_cdst[MAXE];
__device__ int g_ndeg[NN], g_incoff[NN];
__device__ int g_inc[2 * MAXE];
__device__ float g_dinv[MAXE];
__device__ float g_xW[NN * 64];
__device__ float g_aggN[NN * 64];
__device__ double g_p1[G * 64], g_p2[G * 64];
__device__ float g_mu[64], g_istd[64];
__device__ float g_h2[MAXE], g_agg2[NN], g_score[MAXE];
__device__ unsigned g_keyv[MAXE];
__device__ int g_hist[256];
__device__ unsigned long long g_packed[NN];
__device__ int g_bcnt[G], g_boff[G];
__device__ int g_n2c[NN], g_flag[NN], g_rankv[NN], g_uniq[NN], g_ni[NN];
__device__ int g_pcnt[NN], g_poff[NN], g_pnode[NN];
__device__ int g_ecnt[NN], g_eoffA[NN], g_ucnt[NN], g_eoffB[NN];
__device__ int g_E, g_M, g_P, g_krem;
__device__ unsigned g_prefix;

/* ------------------------------ grid barrier ------------------------------ */
__device__ __forceinline__ void gsync() {
    __syncthreads();
    if (threadIdx.x == 0) {
        int gen = *(volatile int*)&g_bar_gen;
        __threadfence();
        if (atomicAdd(&g_bar_cnt, 1) == G - 1) {
            g_bar_cnt = 0;
            __threadfence();
            *(volatile int*)&g_bar_gen = gen + 1;
        } else {
            while (*(volatile int*)&g_bar_gen == gen) __nanosleep(64);
        }
    }
    __syncthreads();
}

/* ---------------- block exclusive scan over T threads (shuffle) ---------------- */
__device__ __forceinline__ int bscan_excl(int v, int* sh, int* total) {
    int t = threadIdx.x, lane = t & 31, w = t >> 5;
    int x = v;
    #pragma unroll
    for (int o = 1; o < 32; o <<= 1) { int y = __shfl_up_sync(0xffffffffu, x, o); if (lane >= o) x += y; }
    if (lane == 31) sh[w] = x;
    __syncthreads();
    if (w == 0) {
        int s = (lane < 8) ? sh[lane] : 0;
        #pragma unroll
        for (int o = 1; o < 8; o <<= 1) { int y = __shfl_up_sync(0xffffffffu, s, o); if (lane >= o) s += y; }
        if (lane < 8) sh[lane] = s;
    }
    __syncthreads();
    *total = sh[7];
    int pre = (w == 0) ? 0 : sh[w - 1];
    return pre + x - v;
}

/* ---------------- block-0 exclusive scan over array ---------------- */
__device__ void scan_b0(const int* in, int* out, int n, int code, char* SMEM) {
    if (blockIdx.x != 0) return;
    int* sh = (int*)SMEM;
    int t = threadIdx.x;
    int per = (n + T - 1) / T;
    int lo = t * per; if (lo > n) lo = n;
    int hi = lo + per; if (hi > n) hi = n;
    int s = 0;
    for (int i = lo; i < hi; i++) s += __ldcg(in + i);
    int total;
    int excl = bscan_excl(s, sh, &total);
    if (t == 0) {
        if (code == 1) g_E = total;
        else if (code == 2) g_M = total;
        else if (code == 3) g_P = total;
    }
    int acc = excl;
    for (int i = lo; i < hi; i++) { int v = __ldcg(in + i); out[i] = acc; acc += v; }
}

/* ---------------- radix-select helpers ---------------- */
__device__ void hist_phase(int shift, unsigned maskHi) {
    int E = g_E;
    unsigned P = __ldcg(&g_prefix);
    for (int e = blockIdx.x * T + threadIdx.x; e < E; e += GT) {
        unsigned kk = g_keyv[e];
        if ((kk & maskHi) == (P & maskHi)) atomicAdd(&g_hist[(kk >> shift) & 255], 1);
    }
}
__device__ void pick_b0(int shift, char* SMEM) {
    if (blockIdx.x == 0) {
        int* sh = (int*)SMEM;
        int t = threadIdx.x;
        sh[t] = __ldcg(&g_hist[t]);
        __syncthreads();
        if (t == 0) {
            int krem = __ldcg(&g_krem);
            int cum = 0, chosen = 0;
            for (int b = 255; b >= 0; b--) {
                int h = sh[b];
                if (cum + h >= krem) { chosen = b; break; }
                cum += h;
            }
            g_prefix = __ldcg(&g_prefix) | (((unsigned)chosen) << shift);
            g_krem = krem - cum;
        }
        __syncthreads();
        g_hist[t] = 0;
    }
}

/* ------------------------------ megakernel ------------------------------ */
extern "C" __global__ void __launch_bounds__(T, 3)
mega(const float* __restrict__ x, const float* __restrict__ W1, const float* __restrict__ b1,
     const float* __restrict__ gamma1, const float* __restrict__ beta1,
     const float* __restrict__ W2, const float* __restrict__ b2,
     const int* __restrict__ ei, const int* __restrict__ batch,
     float* __restrict__ out) {
    __shared__ __align__(16) char SMEM[40960];
    const int t = threadIdx.x;
    const int b = blockIdx.x;
    const int gtid = b * T + t;

    /* ---- ph0: init ---- */
    for (int i = gtid; i < NN; i += GT) {
        g_cnt[i] = 0; g_fill1[i] = 0; g_fill2[i] = 0; g_fill3[i] = 0; g_fill4[i] = 0;
        g_ndeg[i] = 0; g_ecnt[i] = 0; g_pcnt[i] = 0; g_flag[i] = 0; g_ucnt[i] = 0;
        g_packed[i] = ~0ull;
    }
    if (gtid < 256) g_hist[gtid] = 0;
    gsync();

    /* ---- ph1: histogram of raw undirected edges by src ---- */
    for (int i = gtid; i < ED; i += GT) {
        int s = ei[i], d = ei[ED + i];
        if (s < d) atomicAdd(&g_cnt[s], 1);
    }
    gsync();

    /* ---- ph2: scan cnt -> offA ---- */
    scan_b0(g_cnt, g_offA, NN, 0, SMEM);
    gsync();

    /* ---- ph3: scatter to buckets ---- */
    for (int i = gtid; i < ED; i += GT) {
        int s = ei[i], d = ei[ED + i];
        if (s < d) {
            int pos = g_offA[s] + atomicAdd(&g_fill1[s], 1);
            g_bucket[pos] = d;
        }
    }
    gsync();

    /* ---- ph4: per-node sort + dedup ---- */
    for (int u = gtid; u < NN; u += GT) {
        int o = g_offA[u], L = g_cnt[u];
        for (int i = 1; i < L; i++) {
            int key = g_bucket[o + i]; int j = i - 1;
            while (j >= 0 && g_bucket[o + j] > key) { g_bucket[o + j + 1] = g_bucket[o + j]; j--; }
            g_bucket[o + j + 1] = key;
        }
        int m = 0;
        for (int i = 0; i < L; i++) {
            int v = g_bucket[o + i];
            if (m == 0 || v != g_bucket[o + m - 1]) g_bucket[o + m++] = v;
        }
        g_cnt[u] = m;
    }
    gsync();

    /* ---- ph5: scan deduped counts -> offB, total E ---- */
    scan_b0(g_cnt, g_offB, NN, 1, SMEM);
    gsync();

    /* ---- ph6: compact clean edge list + node degrees ---- */
    for (int u = gtid; u < NN; u += GT) {
        int L = g_cnt[u], ob = g_offB[u], oa = g_offA[u];
        for (int j = 0; j < L; j++) {
            int d = g_bucket[oa + j];
            g_csrc[ob + j] = u; g_cdst[ob + j] = d;
            atomicAdd(&g_ndeg[d], 1);
        }
        if (L) atomicAdd(&g_ndeg[u], L);
    }
    gsync();

    /* ---- ph7: scan ndeg -> incoff ---- */
    scan_b0(g_ndeg, g_incoff, NN, 0, SMEM);
    gsync();

    /* ---- ph8: incidence scatter + dinv ---- */
    {
        int E = g_E;
        for (int e = gtid; e < E; e += GT) {
            int u = g_csrc[e], v = g_cdst[e];
            int p1 = g_incoff[u] + atomicAdd(&g_fill2[u], 1); g_inc[p1] = e;
            int p2 = g_incoff[v] + atomicAdd(&g_fill2[v], 1); g_inc[p2] = e;
            int deg = g_ndeg[u] + g_ndeg[v] - 1;
            if (deg < 1) deg = 1;
            g_dinv[e] = 1.0f / sqrtf((float)deg);
        }
    }
    gsync();

    /* ---- ph9: incidence sorts  +  ph10: xW = x @ W1 (independent, merged) ---- */
    for (int u = gtid; u < NN; u += GT) {
        int o = g_incoff[u], L = g_ndeg[u];
        for (int i = 1; i < L; i++) {
            int key = g_inc[o + i]; int j = i - 1;
            while (j >= 0 && g_inc[o + j] > key) { g_inc[o + j + 1] = g_inc[o + j]; j--; }
            g_inc[o + j + 1] = key;
        }
    }
    {
        float* sW = (float*)SMEM;                 /* 128*64 = 32KB */
        float* sx = (float*)(SMEM + 32768);       /* 4*128  = 2KB  */
        __syncthreads();
        for (int i = t; i < 128 * 64; i += T) sW[i] = W1[i];
        __syncthreads();
        for (int grp = b; grp < NN / 4; grp += G) {
            int r0 = grp * 4;
            for (int i = t; i < 4 * 128; i += T) {
                int rr = i >> 7, kk = i & 127;
                sx[rr * 128 + kk] = x[(r0 + rr) * 128 + kk];
            }
            __syncthreads();
            int c = t & 63, rr = t >> 6;
            float acc = 0.f;
            #pragma unroll
            for (int k2 = 0; k2 < 128; k2++) acc += sx[rr * 128 + k2] * sW[k2 * 64 + c];
            g_xW[(r0 + rr) * 64 + c] = acc;
            __syncthreads();
        }
    }
    gsync();

    /* ---- ph11: aggN[n,c] = sum_{e inc n} dinv_e * 0.5*(xW[u]+xW[v]) ---- */
    for (int idx = gtid; idx < NN * 64; idx += GT) {
        int n = idx >> 6, c = idx & 63;
        int o = g_incoff[n], L = g_ndeg[n];
        float s = 0.f;
        for (int j = 0; j < L; j++) {
            int e = g_inc[o + j];
            float h = 0.5f * (g_xW[g_csrc[e] * 64 + c] + g_xW[g_cdst[e] * 64 + c]);
            s += g_dinv[e] * h;
        }
        g_aggN[idx] = s;
    }
    gsync();

    /* ---- ph12: BN stats over conv1 output (recomputed on the fly) ---- */
    {
        int E = g_E;
        double s = 0.0, s2 = 0.0;
        float bc = b1[t & 63];
        for (int idx = gtid; idx < E * 64; idx += GT) {
            int e = idx >> 6, c = idx & 63;
            int u = g_csrc[e], v = g_cdst[e];
            float di = g_dinv[e];
            float h = 0.5f * (g_xW[u * 64 + c] + g_xW[v * 64 + c]);
            float z = di * (g_aggN[u * 64 + c] + g_aggN[v * 64 + c]) - di * di * h + bc;
            double zd = (double)z;
            s += zd; s2 += zd * zd;
        }
        double* sA = (double*)SMEM;
        double* sB = (double*)(SMEM + 2048);
        sA[t] = s; sB[t] = s2;
        __syncthreads();
        if (t < 64) {
            g_p1[b * 64 + t] = sA[t] + sA[t + 64] + sA[t + 128] + sA[t + 192];
            g_p2[b * 64 + t] = sB[t] + sB[t + 64] + sB[t + 128] + sB[t + 192];
        }
    }
    gsync();

    /* ---- ph13: BN finalize + top-k init ---- */
    if (b == 0 && t < 64) {
        double s = 0.0, s2 = 0.0;
        for (int bb = 0; bb < G; bb++) { s += g_p1[bb * 64 + t]; s2 += g_p2[bb * 64 + t]; }
        double Ed = (double)g_E;
        double mu = s / Ed;
        double var = s2 / Ed - mu * mu;
        g_mu[t] = (float)mu;
        g_istd[t] = (float)(1.0 / sqrt(var + 1e-5));
        if (t == 0) {
            int E = g_E;
            int k = E / 2;
            if (k > NN / 2) k = NN / 2;
            if (k < 1) k = 1;
            g_krem = k; g_prefix = 0u;
        }
    }
    gsync();

    /* ---- ph14: BN+ReLU+dot -> h2 (conv1 recomputed) ---- */
    {
        int E = g_E;
        int lane = t & 31;
        float ga0 = gamma1[lane],      be0 = beta1[lane],      w20 = W2[lane],      bb0 = b1[lane];
        float ga1 = gamma1[lane + 32], be1 = beta1[lane + 32], w21 = W2[lane + 32], bb1 = b1[lane + 32];
        float mu0 = g_mu[lane], is0 = g_istd[lane], mu1 = g_mu[lane + 32], is1 = g_istd[lane + 32];
        for (int gt = gtid; gt < E * 32; gt += GT) {
            int e = gt >> 5;
            int u = g_csrc[e], v = g_cdst[e];
            float di = g_dinv[e], di2 = di * di;
            float h0 = 0.5f * (g_xW[u * 64 + lane] + g_xW[v * 64 + lane]);
            float z0 = di * (g_aggN[u * 64 + lane] + g_aggN[v * 64 + lane]) - di2 * h0 + bb0;
            float h1 = 0.5f * (g_xW[u * 64 + 32 + lane] + g_xW[v * 64 + 32 + lane]);
            float z1 = di * (g_aggN[u * 64 + 32 + lane] + g_aggN[v * 64 + 32 + lane]) - di2 * h1 + bb1;
            float a0 = fmaxf(ga0 * (z0 - mu0) * is0 + be0, 0.f);
            float a1 = fmaxf(ga1 * (z1 - mu1) * is1 + be1, 0.f);
            float d = a0 * w20 + a1 * w21;
            #pragma unroll
            for (int o = 16; o > 0; o >>= 1) d += __shfl_down_sync(0xffffffffu, d, o);
            if (lane == 0) g_h2[e] = d;
        }
    }
    gsync();

    /* ---- ph15: agg2 per node ---- */
    for (int n = gtid; n < NN; n += GT) {
        int o = g_incoff[n], L = g_ndeg[n];
        float s = 0.f;
        for (int j = 0; j < L; j++) { int e = g_inc[o + j]; s += g_dinv[e] * g_h2[e]; }
        g_agg2[n] = s;
    }
    gsync();

    /* ---- ph16: scores + radix hist pass 0 ---- */
    {
        int E = g_E;
        float bias2 = b2[0];
        for (int e = gtid; e < E; e += GT) {
            float di = g_dinv[e];
            float z = di * (g_agg2[g_csrc[e]] + g_agg2[g_cdst[e]]) - di * di * g_h2[e] + bias2;
            float s = 1.0f / (1.0f + expf(-z));
            g_score[e] = s;
            unsigned kk = __float_as_uint(s);
            g_keyv[e] = kk;
            atomicAdd(&g_hist[(kk >> 24) & 255], 1);
        }
    }
    gsync();

    /* ---- radix select passes ---- */
    pick_b0(24, SMEM); gsync();
    hist_phase(16, 0xFF000000u); gsync();
    pick_b0(16, SMEM); gsync();
    hist_phase(8, 0xFFFF0000u); gsync();
    pick_b0(8, SMEM); gsync();
    hist_phase(0, 0xFFFFFF00u); gsync();
    pick_b0(0, SMEM); gsync();

    /* ---- ph24: strictly-greater -> atomicMin cluster; count eq per block ---- */
    {
        int E = g_E;
        unsigned Tp = __ldcg(&g_prefix);
        int cb = (E + G - 1) / G;
        int lo = b * cb, hi = lo + cb; if (hi > E) hi = E;
        int cnt = 0;
        for (int base = lo; base < hi; base += T) {
            int i = base + t;
            if (i < hi) {
                unsigned kk = g_keyv[i];
                if (kk > Tp) {
                    unsigned long long pk = (((unsigned long long)kk) << 32) | (unsigned)(0xFFFFFFFFu - (unsigned)i);
                    atomicMin(&g_packed[g_cdst[i]], pk);
                }
                if (kk == Tp) cnt++;
            }
        }
        int* sh = (int*)SMEM;
        int total;
        bscan_excl(cnt, sh, &total);
        if (t == 0) g_bcnt[b] = total;
    }
    gsync();

    /* ---- ph25: scan bcnt -> boff ---- */
    scan_b0(g_bcnt, g_boff, G, 0, SMEM);
    gsync();

    /* ---- ph26: eq keys, index-ordered rank < krem -> select ---- */
    {
        int E = g_E;
        unsigned Tp = __ldcg(&g_prefix);
        int krem = __ldcg(&g_krem);
        int cb = (E + G - 1) / G;
        int lo = b * cb, hi = lo + cb; if (hi > E) hi = E;
        int* ws = (int*)SMEM;
        int* scarry = (int*)SMEM + 16;
        if (t == 0) *scarry = 0;
        __syncthreads();
        int lane = t & 31, wid = t >> 5;
        for (int base = lo; base < hi; base += T) {
            int i = base + t;
            int eq = (i < hi && g_keyv[i] == Tp) ? 1 : 0;
            unsigned bal = __ballot_sync(0xffffffffu, eq);
            if (lane == 0) ws[wid] = __popc(bal);
            __syncthreads();
            int pre = 0;
            for (int k = 0; k < wid; k++) pre += ws[k];
            int lexcl = pre + __popc(bal & ((1u << lane) - 1u));
            if (eq) {
                int rank = g_boff[b] + *scarry + lexcl;
                if (rank < krem) {
                    unsigned long long pk = (((unsigned long long)Tp) << 32) | (unsigned)(0xFFFFFFFFu - (unsigned)i);
                    atomicMin(&g_packed[g_cdst[i]], pk);
                }
            }
            __syncthreads();
            if (t == 0) {
                int tot = 0;
                #pragma unroll
                for (int k = 0; k < 8; k++) tot += ws[k];
                *scarry += tot;
            }
            __syncthreads();
        }
    }
    gsync();

    /* ---- ph27: node -> cluster label ---- */
    for (int n = gtid; n < NN; n += GT) {
        unsigned long long pk = g_packed[n];
        int v;
        if (pk != ~0ull) {
            unsigned e = 0xFFFFFFFFu - (unsigned)(pk & 0xFFFFFFFFull);
            v = g_csrc[e];
        } else v = n;
        g_n2c[n] = v;
        g_flag[v] = 1;
    }
    gsync();

    /* ---- ph28: scan flag -> rankv, total M ---- */
    scan_b0(g_flag, g_rankv, NN, 2, SMEM);
    gsync();

    /* ---- ph29: maps + pool counts ---- */
    for (int n = gtid; n < NN; n += GT) {
        if (g_flag[n]) g_uniq[g_rankv[n]] = n;
        int m = g_rankv[g_n2c[n]];
        g_ni[n] = m;
        atomicAdd(&g_pcnt[m], 1);
    }
    gsync();

    /* ---- ph30: scan pcnt -> poff ---- */
    scan_b0(g_pcnt, g_poff, NN, 0, SMEM);
    gsync();

    /* ---- ph31: scatter members + pooled-edge histogram (independent, merged) ---- */
    for (int n = gtid; n < NN; n += GT) {
        int m = g_ni[n];
        int pos = g_poff[m] + atomicAdd(&g_fill3[m], 1);
        g_pnode[pos] = n;
    }
    for (int i = gtid; i < ED; i += GT) {
        int ns = g_ni[ei[i]], nd = g_ni[ei[ED + i]];
        if (ns != nd) atomicAdd(&g_ecnt[ns], 1);
    }
    gsync();

    /* ---- ph32: scan ecnt -> eoffA (b0)  +  member-list sorts (merged) ---- */
    scan_b0(g_ecnt, g_eoffA, NN, 0, SMEM);
    {
        int M = g_M;
        for (int m = gtid; m < M; m += GT) {
            int o = g_poff[m], L = g_pcnt[m];
            for (int i = 1; i < L; i++) {
                int key = g_pnode[o + i]; int j = i - 1;
                while (j >= 0 && g_pnode[o + j] > key) { g_pnode[o + j + 1] = g_pnode[o + j]; j--; }
                g_pnode[o + j + 1] = key;
            }
        }
    }
    gsync();

    /* ---- ph33: x_pool + scatter pooled edges (independent, merged) ---- */
    {
        int M = g_M;
        for (int idx = gtid; idx < M * 128; idx += GT) {
            int m = idx >> 7, c = idx & 127;
            int o = g_poff[m], L = g_pcnt[m];
            float s = 0.f;
            for (int j = 0; j < L; j++) s += x[g_pnode[o + j] * 128 + c];
            out[m * 128 + c] = s / (float)L;
        }
    }
    for (int i = gtid; i < ED; i += GT) {
        int ns = g_ni[ei[i]], nd = g_ni[ei[ED + i]];
        if (ns != nd) {
            int pos = g_eoffA[ns] + atomicAdd(&g_fill4[ns], 1);
            g_bucket[pos] = nd;
        }
    }
    gsync();

    /* ---- ph37: per-cluster dedup (fused count+compact, small/large split) ---- */
    {
        int M = g_M;
        /* small clusters: one thread each, register insertion sort */
        for (int m = gtid; m < M; m += GT) {
            int L = g_ecnt[m];
            if (L <= SMALL_L) {
                int o = g_eoffA[m];
                int buf[SMALL_L];
                for (int i = 0; i < L; i++) buf[i] = __ldcg(&g_bucket[o + i]);
                for (int i = 1; i < L; i++) {
                    int key = buf[i]; int j = i - 1;
                    while (j >= 0 && buf[j] > key) { buf[j + 1] = buf[j]; j--; }
                    buf[j + 1] = key;
                }
                int u = 0;
                for (int i = 0; i < L; i++) if (u == 0 || buf[i] != buf[u - 1]) buf[u++] = buf[i];
                for (int i = 0; i < u; i++) g_bucket[o + i] = buf[i];
                g_ucnt[m] = u;
            }
        }
        /* large clusters: one block each, bitmask + compact emit */
        unsigned* mask = (unsigned*)SMEM;              /* 2500 bytes */
        int* wsum = (int*)(SMEM + 2560);
        for (int m = b; m < M; m += G) {
            int L = g_ecnt[m];
            if (L <= SMALL_L) continue;
            int o = g_eoffA[m];
            __syncthreads();
            for (int w = t; w < MW; w += T) mask[w] = 0u;
            __syncthreads();
            for (int j = t; j < L; j += T) {
                int nd = __ldcg(&g_bucket[o + j]);
                atomicOr(&mask[nd >> 5], 1u << (nd & 31));
            }
            __syncthreads();
            int w0 = t * 3, ls = 0;
            #pragma unroll
            for (int k = 0; k < 3; k++) { int w = w0 + k; if (w < MW) ls += __popc(mask[w]); }
            int total;
            int off2 = bscan_excl(ls, wsum, &total);
            if (t == 0) g_ucnt[m] = total;
            #pragma unroll
            for (int k = 0; k < 3; k++) {
                int w = w0 + k; if (w >= MW) break;
                unsigned mw = mask[w];
                while (mw) {
                    int bit = __ffs(mw) - 1;
                    g_bucket[o + off2] = w * 32 + bit;
                    off2++;
                    mw &= mw - 1u;
                }
            }
            __syncthreads();
        }
    }
    gsync();

    /* ---- ph38: scan ucnt -> eoffB, total P ---- */
    scan_b0(g_ucnt, g_eoffB, NN, 3, SMEM);
    gsync();

    /* ---- ph39: emit pooled edges (plain copy of compacted lists) ---- */
    {
        int M = g_M;
        long base = 128L * M;
        int P = g_P;
        for (int m = b; m < M; m += G) {
            int o = g_eoffA[m], u = g_ucnt[m], ob = g_eoffB[m];
            for (int j = t; j < u; j += T) {
                int nd = __ldcg(&g_bucket[o + j]);
                out[base + ob + j] = (float)m;
                out[base + (long)P + ob + j] = (float)nd;
            }
        }
    }
    gsync();

    /* ---- ph40: tail outputs ---- */
    {
        int E = g_E, M = g_M, P = g_P;
        long base = 128L * M + 2L * P;
        for (int i = gtid; i < MAXE; i += GT) {
            if (i < M) out[base + i] = (float)batch[g_uniq[i]];
            if (i < E) out[base + M + i] = g_score[i];
            if (i < NN) out[base + M + E + i] = (float)g_ni[i];
        }
    }
}

/* ------------------------------ launch ------------------------------ */
extern "C" void kernel_launch(void* const* d_in, const int* in_sizes, int n_in,
                              void* d_out, int out_size) {
    const float* x      = (const float*)d_in[0];
    const float* W1     = (const float*)d_in[1];
    const float* b1     = (const float*)d_in[2];
    const float* gamma1 = (const float*)d_in[3];
    const float* beta1  = (const float*)d_in[4];
    const float* W2     = (const float*)d_in[5];
    const float* b2     = (const float*)d_in[6];
    const int*   ei     = (const int*)d_in[7];
    const int*   batch  = (const int*)d_in[8];
    float* out = (float*)d_out;

    mega<<<G, T>>>(x, W1, b1, gamma1, beta1, W2, b2, ei, batch, out);

    (void)in_sizes; (void)n_in; (void)out_size;
}

// round 10
// speedup vs baseline: 1.5344x; 1.0197x over previous
#include <cuda_runtime.h>
#include <math.h>

#define NN 20000
#define ED 160000
#define MAXE 160000
#define G 444
#define T 256
#define GT (G * T)
#define MW 625   /* bitmask words for NN bits */
#define SMALL_L 16

/* ------------------------------ scratch ------------------------------ */
__device__ int g_bar_cnt = 0;
__device__ int g_bar_gen = 0;

__device__ int g_cnt[NN], g_fill1[NN], g_fill2[NN], g_fill3[NN], g_fill4[NN];
__device__ int g_offA[NN], g_offB[NN];
__device__ int g_bucket[ED];
__device__ int g_csrc[MAXE], g_cdst[MAXE];
__device__ int g_ndeg[NN], g_incoff[NN];
__device__ int g_inc[2 * MAXE];
__device__ int g_inco[2 * MAXE];
__device__ float g_incd[2 * MAXE];
__device__ float g_dinv[MAXE];
__device__ float g_xW[NN * 64];
__device__ float g_aggN[NN * 64];
__device__ double g_p1[G * 64], g_p2[G * 64];
__device__ float g_mu[64], g_istd[64];
__device__ float g_h2[MAXE], g_agg2[NN], g_score[MAXE];
__device__ unsigned g_keyv[MAXE];
__device__ int g_hist2[65536];
__device__ unsigned long long g_packed[NN];
__device__ int g_bcnt[G], g_boff[G];
__device__ int g_n2c[NN], g_flag[NN], g_rankv[NN], g_uniq[NN], g_ni[NN];
__device__ int g_pcnt[NN], g_poff[NN], g_pnode[NN];
__device__ int g_ecnt[NN], g_eoffA[NN], g_ucnt[NN], g_eoffB[NN];
__device__ int g_E, g_M, g_P, g_krem;
__device__ unsigned g_prefix;

/* ------------------------------ grid barrier ------------------------------ */
__device__ __forceinline__ void gsync() {
    __syncthreads();
    if (threadIdx.x == 0) {
        int gen = *(volatile int*)&g_bar_gen;
        __threadfence();
        if (atomicAdd(&g_bar_cnt, 1) == G - 1) {
            g_bar_cnt = 0;
            __threadfence();
            *(volatile int*)&g_bar_gen = gen + 1;
        } else {
            while (*(volatile int*)&g_bar_gen == gen) __nanosleep(64);
        }
    }
    __syncthreads();
}

/* ---------------- block exclusive scan over T threads (shuffle) ---------------- */
__device__ __forceinline__ int bscan_excl(int v, int* sh, int* total) {
    int t = threadIdx.x, lane = t & 31, w = t >> 5;
    int x = v;
    #pragma unroll
    for (int o = 1; o < 32; o <<= 1) { int y = __shfl_up_sync(0xffffffffu, x, o); if (lane >= o) x += y; }
    if (lane == 31) sh[w] = x;
    __syncthreads();
    if (w == 0) {
        int s = (lane < 8) ? sh[lane] : 0;
        #pragma unroll
        for (int o = 1; o < 8; o <<= 1) { int y = __shfl_up_sync(0xffffffffu, s, o); if (lane >= o) s += y; }
        if (lane < 8) sh[lane] = s;
    }
    __syncthreads();
    *total = sh[7];
    int pre = (w == 0) ? 0 : sh[w - 1];
    return pre + x - v;
}

/* ---------------- block-0 exclusive scan over array ---------------- */
__device__ void scan_b0(const int* in, int* out, int n, int code, char* SMEM) {
    if (blockIdx.x != 0) return;
    int* sh = (int*)SMEM;
    int t = threadIdx.x;
    int per = (n + T - 1) / T;
    int lo = t * per; if (lo > n) lo = n;
    int hi = lo + per; if (hi > n) hi = n;
    int s = 0;
    for (int i = lo; i < hi; i++) s += __ldcg(in + i);
    int total;
    int excl = bscan_excl(s, sh, &total);
    if (t == 0) {
        if (code == 1) g_E = total;
        else if (code == 2) g_M = total;
        else if (code == 3) g_P = total;
    }
    int acc = excl;
    for (int i = lo; i < hi; i++) { int v = __ldcg(in + i); out[i] = acc; acc += v; }
}

/* ---------------- 16-bit radix pick (block 0) ---------------- */
__device__ void pick16_b0(int hi, char* SMEM) {
    if (blockIdx.x != 0) return;
    int* seg  = (int*)SMEM;          /* 256 */
    int* sbin = (int*)SMEM + 256;    /* 256 */
    int* info = (int*)SMEM + 512;    /* 2   */
    int t = threadIdx.x;
    int s = 0, base = t * 256;
    for (int i = 0; i < 256; i++) s += __ldcg(&g_hist2[base + i]);
    seg[t] = s;
    __syncthreads();
    if (t == 0) {
        int krem = __ldcg(&g_krem);
        int cum = 0, sid = 0;
        for (int sg = 255; sg >= 0; sg--) { int h = seg[sg]; if (cum + h >= krem) { sid = sg; break; } cum += h; }
        info[0] = sid; info[1] = cum;
    }
    __syncthreads();
    int sid = info[0];
    sbin[t] = __ldcg(&g_hist2[sid * 256 + t]);
    __syncthreads();
    if (t == 0) {
        int krem = __ldcg(&g_krem);
        int cum = info[1], chosen = sid * 256;
        for (int bn = 255; bn >= 0; bn--) { int h = sbin[bn]; if (cum + h >= krem) { chosen = sid * 256 + bn; break; } cum += h; }
        g_prefix = __ldcg(&g_prefix) | ((unsigned)chosen << (hi ? 16 : 0));
        g_krem = krem - cum;
    }
    __syncthreads();
    if (hi) for (int i = t; i < 65536; i += T) g_hist2[i] = 0;
}

/* ------------------------------ megakernel ------------------------------ */
extern "C" __global__ void __launch_bounds__(T, 3)
mega(const float* __restrict__ x, const float* __restrict__ W1, const float* __restrict__ b1,
     const float* __restrict__ gamma1, const float* __restrict__ beta1,
     const float* __restrict__ W2, const float* __restrict__ b2,
     const int* __restrict__ ei, const int* __restrict__ batch,
     float* __restrict__ out) {
    __shared__ __align__(16) char SMEM[40960];
    const int t = threadIdx.x;
    const int b = blockIdx.x;
    const int gtid = b * T + t;

    /* ---- ph0: init ---- */
    for (int i = gtid; i < NN; i += GT) {
        g_cnt[i] = 0; g_fill1[i] = 0; g_fill2[i] = 0; g_fill3[i] = 0; g_fill4[i] = 0;
        g_ndeg[i] = 0; g_ecnt[i] = 0; g_pcnt[i] = 0; g_flag[i] = 0; g_ucnt[i] = 0;
        g_packed[i] = ~0ull;
    }
    for (int i = gtid; i < 65536; i += GT) g_hist2[i] = 0;
    gsync();

    /* ---- ph1: histogram of raw undirected edges by src ---- */
    for (int i = gtid; i < ED; i += GT) {
        int s = ei[i], d = ei[ED + i];
        if (s < d) atomicAdd(&g_cnt[s], 1);
    }
    gsync();

    /* ---- ph2: scan cnt -> offA ---- */
    scan_b0(g_cnt, g_offA, NN, 0, SMEM);
    gsync();

    /* ---- ph3: scatter to buckets ---- */
    for (int i = gtid; i < ED; i += GT) {
        int s = ei[i], d = ei[ED + i];
        if (s < d) {
            int pos = g_offA[s] + atomicAdd(&g_fill1[s], 1);
            g_bucket[pos] = d;
        }
    }
    gsync();

    /* ---- ph4: per-node sort + dedup (registerized) ---- */
    for (int u = gtid; u < NN; u += GT) {
        int o = g_offA[u], L = g_cnt[u], m = 0;
        if (L <= 24) {
            int buf[24];
            for (int i = 0; i < L; i++) buf[i] = g_bucket[o + i];
            for (int i = 1; i < L; i++) {
                int key = buf[i]; int j = i - 1;
                while (j >= 0 && buf[j] > key) { buf[j + 1] = buf[j]; j--; }
                buf[j + 1] = key;
            }
            int last = -1;
            for (int i = 0; i < L; i++) {
                int v = buf[i];
                if (v != last) { g_bucket[o + m++] = v; last = v; }
            }
        } else {
            for (int i = 1; i < L; i++) {
                int key = g_bucket[o + i]; int j = i - 1;
                while (j >= 0 && g_bucket[o + j] > key) { g_bucket[o + j + 1] = g_bucket[o + j]; j--; }
                g_bucket[o + j + 1] = key;
            }
            for (int i = 0; i < L; i++) {
                int v = g_bucket[o + i];
                if (m == 0 || v != g_bucket[o + m - 1]) g_bucket[o + m++] = v;
            }
        }
        g_cnt[u] = m;
    }
    gsync();

    /* ---- ph5: scan deduped counts -> offB, total E ---- */
    scan_b0(g_cnt, g_offB, NN, 1, SMEM);
    gsync();

    /* ---- ph6: compact clean edge list + node degrees ---- */
    for (int u = gtid; u < NN; u += GT) {
        int L = g_cnt[u], ob = g_offB[u], oa = g_offA[u];
        for (int j = 0; j < L; j++) {
            int d = g_bucket[oa + j];
            g_csrc[ob + j] = u; g_cdst[ob + j] = d;
            atomicAdd(&g_ndeg[d], 1);
        }
        if (L) atomicAdd(&g_ndeg[u], L);
    }
    gsync();

    /* ---- ph7: scan ndeg -> incoff ---- */
    scan_b0(g_ndeg, g_incoff, NN, 0, SMEM);
    gsync();

    /* ---- ph8: incidence scatter + dinv ---- */
    {
        int E = g_E;
        for (int e = gtid; e < E; e += GT) {
            int u = g_csrc[e], v = g_cdst[e];
            int p1 = g_incoff[u] + atomicAdd(&g_fill2[u], 1); g_inc[p1] = e;
            int p2 = g_incoff[v] + atomicAdd(&g_fill2[v], 1); g_inc[p2] = e;
            int deg = g_ndeg[u] + g_ndeg[v] - 1;
            if (deg < 1) deg = 1;
            g_dinv[e] = 1.0f / sqrtf((float)deg);
        }
    }
    gsync();

    /* ---- ph9: incidence sorts (registerized) + slot (other,dinv) fill + GEMM ---- */
    for (int u = gtid; u < NN; u += GT) {
        int o = g_incoff[u], L = g_ndeg[u];
        if (L <= 32) {
            int buf[32];
            for (int i = 0; i < L; i++) buf[i] = g_inc[o + i];
            for (int i = 1; i < L; i++) {
                int key = buf[i]; int j = i - 1;
                while (j >= 0 && buf[j] > key) { buf[j + 1] = buf[j]; j--; }
                buf[j + 1] = key;
            }
            for (int i = 0; i < L; i++) g_inc[o + i] = buf[i];
            for (int j = 0; j < L; j++) {
                int e = buf[j];
                int uu = g_csrc[e], vv = g_cdst[e];
                g_inco[o + j] = uu + vv - u;
                g_incd[o + j] = g_dinv[e];
            }
        } else {
            for (int i = 1; i < L; i++) {
                int key = g_inc[o + i]; int j = i - 1;
                while (j >= 0 && g_inc[o + j] > key) { g_inc[o + j + 1] = g_inc[o + j]; j--; }
                g_inc[o + j + 1] = key;
            }
            for (int j = 0; j < L; j++) {
                int e = g_inc[o + j];
                int uu = g_csrc[e], vv = g_cdst[e];
                g_inco[o + j] = uu + vv - u;
                g_incd[o + j] = g_dinv[e];
            }
        }
    }
    {
        /* register-tiled GEMM: 16 rows per group, 4 rows per thread */
        float* sW = (float*)SMEM;                 /* 128*64*4 = 32KB */
        float* sx = (float*)(SMEM + 32768);       /* 16*128*4 = 8KB  */
        __syncthreads();
        for (int i = t; i < 128 * 64; i += T) sW[i] = W1[i];
        __syncthreads();
        int c = t & 63, q = t >> 6;
        int rb = q * 4;
        for (int grp = b; grp < NN / 16; grp += G) {
            int r0 = grp * 16;
            float4* sx4 = (float4*)sx;
            const float4* x4 = (const float4*)(x + (long)r0 * 128);
            for (int i = t; i < 512; i += T) sx4[i] = x4[i];
            __syncthreads();
            float a0 = 0.f, a1 = 0.f, a2 = 0.f, a3 = 0.f;
            #pragma unroll 4
            for (int k2 = 0; k2 < 128; k2++) {
                float w = sW[k2 * 64 + c];
                a0 += sx[(rb + 0) * 128 + k2] * w;
                a1 += sx[(rb + 1) * 128 + k2] * w;
                a2 += sx[(rb + 2) * 128 + k2] * w;
                a3 += sx[(rb + 3) * 128 + k2] * w;
            }
            g_xW[(r0 + rb + 0) * 64 + c] = a0;
            g_xW[(r0 + rb + 1) * 64 + c] = a1;
            g_xW[(r0 + rb + 2) * 64 + c] = a2;
            g_xW[(r0 + rb + 3) * 64 + c] = a3;
            __syncthreads();
        }
    }
    gsync();

    /* ---- ph11: aggN via (other,dinv) slots — 2-deep chain, bitwise-identical ---- */
    for (int idx = gtid; idx < NN * 64; idx += GT) {
        int n = idx >> 6, c = idx & 63;
        int o = g_incoff[n], L = g_ndeg[n];
        float xn = g_xW[n * 64 + c];
        float s = 0.f;
        for (int j = 0; j < L; j++) {
            int other = g_inco[o + j];
            float di = g_incd[o + j];
            s += di * (0.5f * (xn + g_xW[other * 64 + c]));
        }
        g_aggN[idx] = s;
    }
    gsync();

    /* ---- ph12: BN stats over conv1 output (recomputed on the fly) ---- */
    {
        int E = g_E;
        double s = 0.0, s2 = 0.0;
        float bc = b1[t & 63];
        for (int idx = gtid; idx < E * 64; idx += GT) {
            int e = idx >> 6, c = idx & 63;
            int u = g_csrc[e], v = g_cdst[e];
            float di = g_dinv[e];
            float h = 0.5f * (g_xW[u * 64 + c] + g_xW[v * 64 + c]);
            float z = di * (g_aggN[u * 64 + c] + g_aggN[v * 64 + c]) - di * di * h + bc;
            double zd = (double)z;
            s += zd; s2 += zd * zd;
        }
        double* sA = (double*)SMEM;
        double* sB = (double*)(SMEM + 2048);
        sA[t] = s; sB[t] = s2;
        __syncthreads();
        if (t < 64) {
            g_p1[b * 64 + t] = sA[t] + sA[t + 64] + sA[t + 128] + sA[t + 192];
            g_p2[b * 64 + t] = sB[t] + sB[t + 64] + sB[t + 128] + sB[t + 192];
        }
    }
    gsync();

    /* ---- ph13: BN finalize + top-k init ---- */
    if (b == 0 && t < 64) {
        double s = 0.0, s2 = 0.0;
        for (int bb = 0; bb < G; bb++) { s += g_p1[bb * 64 + t]; s2 += g_p2[bb * 64 + t]; }
        double Ed = (double)g_E;
        double mu = s / Ed;
        double var = s2 / Ed - mu * mu;
        g_mu[t] = (float)mu;
        g_istd[t] = (float)(1.0 / sqrt(var + 1e-5));
        if (t == 0) {
            int E = g_E;
            int k = E / 2;
            if (k > NN / 2) k = NN / 2;
            if (k < 1) k = 1;
            g_krem = k; g_prefix = 0u;
        }
    }
    gsync();

    /* ---- ph14: BN+ReLU+dot -> h2 (conv1 recomputed) ---- */
    {
        int E = g_E;
        int lane = t & 31;
        float ga0 = gamma1[lane],      be0 = beta1[lane],      w20 = W2[lane],      bb0 = b1[lane];
        float ga1 = gamma1[lane + 32], be1 = beta1[lane + 32], w21 = W2[lane + 32], bb1 = b1[lane + 32];
        float mu0 = g_mu[lane], is0 = g_istd[lane], mu1 = g_mu[lane + 32], is1 = g_istd[lane + 32];
        for (int gt = gtid; gt < E * 32; gt += GT) {
            int e = gt >> 5;
            int u = g_csrc[e], v = g_cdst[e];
            float di = g_dinv[e], di2 = di * di;
            float h0 = 0.5f * (g_xW[u * 64 + lane] + g_xW[v * 64 + lane]);
            float z0 = di * (g_aggN[u * 64 + lane] + g_aggN[v * 64 + lane]) - di2 * h0 + bb0;
            float h1 = 0.5f * (g_xW[u * 64 + 32 + lane] + g_xW[v * 64 + 32 + lane]);
            float z1 = di * (g_aggN[u * 64 + 32 + lane] + g_aggN[v * 64 + 32 + lane]) - di2 * h1 + bb1;
            float a0 = fmaxf(ga0 * (z0 - mu0) * is0 + be0, 0.f);
            float a1 = fmaxf(ga1 * (z1 - mu1) * is1 + be1, 0.f);
            float d = a0 * w20 + a1 * w21;
            #pragma unroll
            for (int o = 16; o > 0; o >>= 1) d += __shfl_down_sync(0xffffffffu, d, o);
            if (lane == 0) g_h2[e] = d;
        }
    }
    gsync();

    /* ---- ph15: agg2 per node ---- */
    for (int n = gtid; n < NN; n += GT) {
        int o = g_incoff[n], L = g_ndeg[n];
        float s = 0.f;
        for (int j = 0; j < L; j++) { int e = g_inc[o + j]; s += g_incd[o + j] * g_h2[e]; }
        g_agg2[n] = s;
    }
    gsync();

    /* ---- ph16: scores + 16-bit radix hist (hi) ---- */
    {
        int E = g_E;
        float bias2 = b2[0];
        for (int e = gtid; e < E; e += GT) {
            float di = g_dinv[e];
            float z = di * (g_agg2[g_csrc[e]] + g_agg2[g_cdst[e]]) - di * di * g_h2[e] + bias2;
            float s = 1.0f / (1.0f + expf(-z));
            g_score[e] = s;
            unsigned kk = __float_as_uint(s);
            g_keyv[e] = kk;
            atomicAdd(&g_hist2[kk >> 16], 1);
        }
    }
    gsync();

    /* ---- ph17: pick hi 16 bits (and zero hist) ---- */
    pick16_b0(1, SMEM);
    gsync();

    /* ---- ph18: hist low 16 bits for matching hi prefix ---- */
    {
        int E = g_E;
        unsigned hiP = __ldcg(&g_prefix) >> 16;
        for (int e = gtid; e < E; e += GT) {
            unsigned kk = g_keyv[e];
            if ((kk >> 16) == hiP) atomicAdd(&g_hist2[kk & 0xFFFFu], 1);
        }
    }
    gsync();

    /* ---- ph19: pick low 16 bits ---- */
    pick16_b0(0, SMEM);
    gsync();

    /* ---- ph24: strictly-greater -> atomicMin cluster; count eq per block ---- */
    {
        int E = g_E;
        unsigned Tp = __ldcg(&g_prefix);
        int cb = (E + G - 1) / G;
        int lo = b * cb, hi = lo + cb; if (hi > E) hi = E;
        int cnt = 0;
        for (int base = lo; base < hi; base += T) {
            int i = base + t;
            if (i < hi) {
                unsigned kk = g_keyv[i];
                if (kk > Tp) {
                    unsigned long long pk = (((unsigned long long)kk) << 32) | (unsigned)(0xFFFFFFFFu - (unsigned)i);
                    atomicMin(&g_packed[g_cdst[i]], pk);
                }
                if (kk == Tp) cnt++;
            }
        }
        int* sh = (int*)SMEM;
        int total;
        bscan_excl(cnt, sh, &total);
        if (t == 0) g_bcnt[b] = total;
    }
    gsync();

    /* ---- ph25: scan bcnt -> boff ---- */
    scan_b0(g_bcnt, g_boff, G, 0, SMEM);
    gsync();

    /* ---- ph26: eq keys, index-ordered rank < krem -> select ---- */
    {
        int E = g_E;
        unsigned Tp = __ldcg(&g_prefix);
        int krem = __ldcg(&g_krem);
        int cb = (E + G - 1) / G;
        int lo = b * cb, hi = lo + cb; if (hi > E) hi = E;
        int* ws = (int*)SMEM;
        int* scarry = (int*)SMEM + 16;
        if (t == 0) *scarry = 0;
        __syncthreads();
        int lane = t & 31, wid = t >> 5;
        for (int base = lo; base < hi; base += T) {
            int i = base + t;
            int eq = (i < hi && g_keyv[i] == Tp) ? 1 : 0;
            unsigned bal = __ballot_sync(0xffffffffu, eq);
            if (lane == 0) ws[wid] = __popc(bal);
            __syncthreads();
            int pre = 0;
            for (int k = 0; k < wid; k++) pre += ws[k];
            int lexcl = pre + __popc(bal & ((1u << lane) - 1u));
            if (eq) {
                int rank = g_boff[b] + *scarry + lexcl;
                if (rank < krem) {
                    unsigned long long pk = (((unsigned long long)Tp) << 32) | (unsigned)(0xFFFFFFFFu - (unsigned)i);
                    atomicMin(&g_packed[g_cdst[i]], pk);
                }
            }
            __syncthreads();
            if (t == 0) {
                int tot = 0;
                #pragma unroll
                for (int k = 0; k < 8; k++) tot += ws[k];
                *scarry += tot;
            }
            __syncthreads();
        }
    }
    gsync();

    /* ---- ph27: node -> cluster label ---- */
    for (int n = gtid; n < NN; n += GT) {
        unsigned long long pk = g_packed[n];
        int v;
        if (pk != ~0ull) {
            unsigned e = 0xFFFFFFFFu - (unsigned)(pk & 0xFFFFFFFFull);
            v = g_csrc[e];
        } else v = n;
        g_n2c[n] = v;
        g_flag[v] = 1;
    }
    gsync();

    /* ---- ph28: scan flag -> rankv, total M ---- */
    scan_b0(g_flag, g_rankv, NN, 2, SMEM);
    gsync();

    /* ---- ph29: maps + pool counts ---- */
    for (int n = gtid; n < NN; n += GT) {
        if (g_flag[n]) g_uniq[g_rankv[n]] = n;
        int m = g_rankv[g_n2c[n]];
        g_ni[n] = m;
        atomicAdd(&g_pcnt[m], 1);
    }
    gsync();

    /* ---- ph30: scan pcnt -> poff ---- */
    scan_b0(g_pcnt, g_poff, NN, 0, SMEM);
    gsync();

    /* ---- ph31: scatter members + pooled-edge histogram (merged) ---- */
    for (int n = gtid; n < NN; n += GT) {
        int m = g_ni[n];
        int pos = g_poff[m] + atomicAdd(&g_fill3[m], 1);
        g_pnode[pos] = n;
    }
    for (int i = gtid; i < ED; i += GT) {
        int ns = g_ni[ei[i]], nd = g_ni[ei[ED + i]];
        if (ns != nd) atomicAdd(&g_ecnt[ns], 1);
    }
    gsync();

    /* ---- ph32: scan ecnt -> eoffA (b0) + member-list sorts (registerized) ---- */
    scan_b0(g_ecnt, g_eoffA, NN, 0, SMEM);
    {
        int M = g_M;
        for (int m = gtid; m < M; m += GT) {
            int o = g_poff[m], L = g_pcnt[m];
            if (L <= 16) {
                int buf[16];
                for (int i = 0; i < L; i++) buf[i] = g_pnode[o + i];
                for (int i = 1; i < L; i++) {
                    int key = buf[i]; int j = i - 1;
                    while (j >= 0 && buf[j] > key) { buf[j + 1] = buf[j]; j--; }
                    buf[j + 1] = key;
                }
                for (int i = 0; i < L; i++) g_pnode[o + i] = buf[i];
            } else {
                for (int i = 1; i < L; i++) {
                    int key = g_pnode[o + i]; int j = i - 1;
                    while (j >= 0 && g_pnode[o + j] > key) { g_pnode[o + j + 1] = g_pnode[o + j]; j--; }
                    g_pnode[o + j + 1] = key;
                }
            }
        }
    }
    gsync();

    /* ---- ph33: x_pool + scatter pooled edges (merged) ---- */
    {
        int M = g_M;
        for (int idx = gtid; idx < M * 128; idx += GT) {
            int m = idx >> 7, c = idx & 127;
            int o = g_poff[m], L = g_pcnt[m];
            float s = 0.f;
            for (int j = 0; j < L; j++) s += x[g_pnode[o + j] * 128 + c];
            out[m * 128 + c] = s / (float)L;
        }
    }
    for (int i = gtid; i < ED; i += GT) {
        int ns = g_ni[ei[i]], nd = g_ni[ei[ED + i]];
        if (ns != nd) {
            int pos = g_eoffA[ns] + atomicAdd(&g_fill4[ns], 1);
            g_bucket[pos] = nd;
        }
    }
    gsync();

    /* ---- ph37: per-cluster dedup (fused count+compact, small/large split) ---- */
    {
        int M = g_M;
        for (int m = gtid; m < M; m += GT) {
            int L = g_ecnt[m];
            if (L <= SMALL_L) {
                int o = g_eoffA[m];
                int buf[SMALL_L];
                for (int i = 0; i < L; i++) buf[i] = __ldcg(&g_bucket[o + i]);
                for (int i = 1; i < L; i++) {
                    int key = buf[i]; int j = i - 1;
                    while (j >= 0 && buf[j] > key) { buf[j + 1] = buf[j]; j--; }
                    buf[j + 1] = key;
                }
                int u = 0;
                for (int i = 0; i < L; i++) if (u == 0 || buf[i] != buf[u - 1]) buf[u++] = buf[i];
                for (int i = 0; i < u; i++) g_bucket[o + i] = buf[i];
                g_ucnt[m] = u;
            }
        }
        unsigned* mask = (unsigned*)SMEM;
        int* wsum = (int*)(SMEM + 2560);
        for (int m = b; m < M; m += G) {
            int L = g_ecnt[m];
            if (L <= SMALL_L) continue;
            int o = g_eoffA[m];
            __syncthreads();
            for (int w = t; w < MW; w += T) mask[w] = 0u;
            __syncthreads();
            for (int j = t; j < L; j += T) {
                int nd = __ldcg(&g_bucket[o + j]);
                atomicOr(&mask[nd >> 5], 1u << (nd & 31));
            }
            __syncthreads();
            int w0 = t * 3, ls = 0;
            #pragma unroll
            for (int k = 0; k < 3; k++) { int w = w0 + k; if (w < MW) ls += __popc(mask[w]); }
            int total;
            int off2 = bscan_excl(ls, wsum, &total);
            if (t == 0) g_ucnt[m] = total;
            #pragma unroll
            for (int k = 0; k < 3; k++) {
                int w = w0 + k; if (w >= MW) break;
                unsigned mw = mask[w];
                while (mw) {
                    int bit = __ffs(mw) - 1;
                    g_bucket[o + off2] = w * 32 + bit;
                    off2++;
                    mw &= mw - 1u;
                }
            }
            __syncthreads();
        }
    }
    gsync();

    /* ---- ph38: scan ucnt -> eoffB, total P ---- */
    scan_b0(g_ucnt, g_eoffB, NN, 3, SMEM);
    gsync();

    /* ---- ph39: emit pooled edges ---- */
    {
        int M = g_M;
        long base = 128L * M;
        int P = g_P;
        for (int m = b; m < M; m += G) {
            int o = g_eoffA[m], u = g_ucnt[m], ob = g_eoffB[m];
            for (int j = t; j < u; j += T) {
                int nd = __ldcg(&g_bucket[o + j]);
                out[base + ob + j] = (float)m;
                out[base + (long)P + ob + j] = (float)nd;
            }
        }
    }
    gsync();

    /* ---- ph40: tail outputs ---- */
    {
        int E = g_E, M = g_M, P = g_P;
        long base = 128L * M + 2L * P;
        for (int i = gtid; i < MAXE; i += GT) {
            if (i < M) out[base + i] = (float)batch[g_uniq[i]];
            if (i < E) out[base + M + i] = g_score[i];
            if (i < NN) out[base + M + E + i] = (float)g_ni[i];
        }
    }
}

/* ------------------------------ launch ------------------------------ */
extern "C" void kernel_launch(void* const* d_in, const int* in_sizes, int n_in,
                              void* d_out, int out_size) {
    const float* x      = (const float*)d_in[0];
    const float* W1     = (const float*)d_in[1];
    const float* b1     = (const float*)d_in[2];
    const float* gamma1 = (const float*)d_in[3];
    const float* beta1  = (const float*)d_in[4];
    const float* W2     = (const float*)d_in[5];
    const float* b2     = (const float*)d_in[6];
    const int*   ei     = (const int*)d_in[7];
    const int*   batch  = (const int*)d_in[8];
    float* out = (float*)d_out;

    mega<<<G, T>>>(x, W1, b1, gamma1, beta1, W2, b2, ei, batch, out);

    (void)in_sizes; (void)n_in; (void)out_size;
}